// round 3
// baseline (speedup 1.0000x reference)
#include <cuda_runtime.h>
#include <math.h>

#define BB 2
#define SS 4096
#define DMD 768
#define NH 12
#define HDD 64
#define MROWS (BB*SS)

// Scratch (static device globals — allocation-free rule)
__device__ float g_q[MROWS*DMD];
__device__ float g_k[MROWS*DMD];
__device__ float g_v[MROWS*DMD];
__device__ float g_attn[MROWS*DMD];
__device__ float g_tmp[MROWS*DMD];

// ---------------------------------------------------------------------------
// GEMM: out[M,N] = X[M,K] @ W[N,K]^T (+ bias[N]) (+ residual[M,N])
// M=8192, N=K=768.  64x64 tile, BK=16, 256 threads, 4x4 micro-tile.
// ---------------------------------------------------------------------------
__global__ __launch_bounds__(256) void gemm_xwt(
    const float* __restrict__ X, const float* __restrict__ W,
    const float* __restrict__ bias, const float* __restrict__ residual,
    float* __restrict__ out)
{
    const int K = DMD, N = DMD;
    __shared__ float As[16][64];   // [k][row]
    __shared__ float Bs[16][64];   // [k][col]
    const int tid = threadIdx.x;
    const int tx  = tid & 15;
    const int ty  = tid >> 4;
    const int row0 = blockIdx.y * 64;
    const int col0 = blockIdx.x * 64;
    const int lr = tid >> 2;          // 0..63
    const int lk = (tid & 3) * 4;     // 0,4,8,12

    float acc[4][4] = {};

    for (int k0 = 0; k0 < K; k0 += 16) {
        __syncthreads();
        float4 xv = *(const float4*)&X[(size_t)(row0 + lr) * K + k0 + lk];
        As[lk+0][lr]=xv.x; As[lk+1][lr]=xv.y; As[lk+2][lr]=xv.z; As[lk+3][lr]=xv.w;
        float4 wv = *(const float4*)&W[(size_t)(col0 + lr) * K + k0 + lk];
        Bs[lk+0][lr]=wv.x; Bs[lk+1][lr]=wv.y; Bs[lk+2][lr]=wv.z; Bs[lk+3][lr]=wv.w;
        __syncthreads();
        #pragma unroll
        for (int kk = 0; kk < 16; kk++) {
            float a[4], b[4];
            *(float4*)a = *(const float4*)&As[kk][ty*4];
            *(float4*)b = *(const float4*)&Bs[kk][tx*4];
            #pragma unroll
            for (int i = 0; i < 4; i++)
                #pragma unroll
                for (int j = 0; j < 4; j++)
                    acc[i][j] += a[i] * b[j];
        }
    }

    #pragma unroll
    for (int i = 0; i < 4; i++) {
        const int r = row0 + ty*4 + i;
        #pragma unroll
        for (int j = 0; j < 4; j++) {
            const int c = col0 + tx*4 + j;
            float v = acc[i][j];
            if (bias)     v += bias[c];
            if (residual) v += residual[(size_t)r * N + c];
            out[(size_t)r * N + c] = v;
        }
    }
}

// ---------------------------------------------------------------------------
// RoPE (in-place) on q and k.  q additionally scaled by SCALING^2 = 1/HD.
// One thread per (b, s, h, d<32) pair.
// ---------------------------------------------------------------------------
__global__ __launch_bounds__(256) void rope_kernel(
    float* __restrict__ q, float* __restrict__ k,
    const float* __restrict__ cosb, const float* __restrict__ sinb)
{
    int idx = blockIdx.x * blockDim.x + threadIdx.x;   // over BB*SS*NH*32
    int d = idx & 31;
    int h = (idx >> 5) % NH;
    int s = (idx >> 5) / NH % SS;
    int b = idx / (32 * NH * SS);
    size_t base = ((size_t)(b * SS + s)) * DMD + h * HDD;
    float c1 = cosb[s*HDD + d],      s1 = sinb[s*HDD + d];
    float c2 = cosb[s*HDD + d + 32], s2 = sinb[s*HDD + d + 32];

    const float qs = 1.0f / (float)HDD;   // SCALING * SCALING
    float q1 = q[base + d], q2 = q[base + d + 32];
    q[base + d]      = (q1*c1 - q2*s1) * qs;
    q[base + d + 32] = (q2*c2 + q1*s2) * qs;

    float k1 = k[base + d], k2 = k[base + d + 32];
    k[base + d]      = k1*c1 - k2*s1;
    k[base + d + 32] = k2*c2 + k1*s2;
}

// ---------------------------------------------------------------------------
// Flash attention (fp32, no mask). Block = 64 queries; loop over 64-wide KV
// tiles with online softmax. 256 threads (16x16), 4x4 micro-tiles.
// Layouts: Q/K/V/O all [B, S, DM] with head h at column h*64.
// ---------------------------------------------------------------------------
#define ATTN_SMEM ((3*64*64 + 64*68) * 4)

__global__ __launch_bounds__(256) void attn_kernel(
    const float* __restrict__ Q, const float* __restrict__ K,
    const float* __restrict__ V, float* __restrict__ O)
{
    extern __shared__ float sm[];
    float* Qs = sm;                 // [d][r]  64x64
    float* Ks = sm + 64*64;         // [d][c]  64x64
    float* Vs = sm + 2*64*64;       // [c][d]  64x64
    float* Ps = sm + 3*64*64;       // [r][c]  64x68 (padded)

    const int tid = threadIdx.x;
    const int tx = tid & 15;
    const int ty = tid >> 4;
    const int bh = blockIdx.y;
    const int b = bh / NH, h = bh % NH;
    const int s0 = blockIdx.x * 64;

    const float* Qb = Q + (size_t)b * SS * DMD + h * HDD;
    const float* Kb = K + (size_t)b * SS * DMD + h * HDD;
    const float* Vb = V + (size_t)b * SS * DMD + h * HDD;

    // Load Q tile (transposed into Qs[d][r])
    #pragma unroll
    for (int it = 0; it < 4; it++) {
        int idx = tid + it * 256;          // 0..1023
        int r  = idx >> 4;                 // 0..63
        int dq = (idx & 15) * 4;           // 0..60
        float4 qv = *(const float4*)&Qb[(size_t)(s0 + r) * DMD + dq];
        Qs[(dq+0)*64 + r] = qv.x; Qs[(dq+1)*64 + r] = qv.y;
        Qs[(dq+2)*64 + r] = qv.z; Qs[(dq+3)*64 + r] = qv.w;
    }

    float o[4][4] = {};
    float m_i[4], l_i[4];
    #pragma unroll
    for (int i = 0; i < 4; i++) { m_i[i] = -1e30f; l_i[i] = 0.0f; }

    for (int t0 = 0; t0 < SS; t0 += 64) {
        __syncthreads();   // previous tile fully consumed (also covers Q-tile store)
        #pragma unroll
        for (int it = 0; it < 4; it++) {
            int idx = tid + it * 256;
            int c  = idx >> 4;
            int dq = (idx & 15) * 4;
            float4 kv = *(const float4*)&Kb[(size_t)(t0 + c) * DMD + dq];
            Ks[(dq+0)*64 + c] = kv.x; Ks[(dq+1)*64 + c] = kv.y;
            Ks[(dq+2)*64 + c] = kv.z; Ks[(dq+3)*64 + c] = kv.w;
            float4 vv = *(const float4*)&Vb[(size_t)(t0 + c) * DMD + dq];
            *(float4*)&Vs[c*64 + dq] = vv;
        }
        __syncthreads();

        // S = Q K^T   (q already carries 1/HD scale)
        float s[4][4] = {};
        #pragma unroll 16
        for (int d = 0; d < 64; d++) {
            float a[4], bb[4];
            *(float4*)a  = *(const float4*)&Qs[d*64 + ty*4];
            *(float4*)bb = *(const float4*)&Ks[d*64 + tx*4];
            #pragma unroll
            for (int i = 0; i < 4; i++)
                #pragma unroll
                for (int j = 0; j < 4; j++)
                    s[i][j] += a[i] * bb[j];
        }

        // Online softmax (row stats reduced across the 16 tx lanes)
        #pragma unroll
        for (int i = 0; i < 4; i++) {
            float mx = s[i][0];
            #pragma unroll
            for (int j = 1; j < 4; j++) mx = fmaxf(mx, s[i][j]);
            #pragma unroll
            for (int off = 8; off > 0; off >>= 1)
                mx = fmaxf(mx, __shfl_xor_sync(0xffffffffu, mx, off));
            float mnew = fmaxf(m_i[i], mx);
            float fcor = __expf(m_i[i] - mnew);
            float psum = 0.0f;
            #pragma unroll
            for (int j = 0; j < 4; j++) {
                s[i][j] = __expf(s[i][j] - mnew);
                psum += s[i][j];
            }
            #pragma unroll
            for (int off = 8; off > 0; off >>= 1)
                psum += __shfl_xor_sync(0xffffffffu, psum, off);
            l_i[i] = l_i[i] * fcor + psum;
            m_i[i] = mnew;
            #pragma unroll
            for (int j = 0; j < 4; j++) o[i][j] *= fcor;
        }

        // P to shared
        #pragma unroll
        for (int i = 0; i < 4; i++)
            *(float4*)&Ps[(ty*4 + i)*68 + tx*4] =
                make_float4(s[i][0], s[i][1], s[i][2], s[i][3]);
        __syncthreads();

        // O += P V
        #pragma unroll
        for (int c4 = 0; c4 < 64; c4 += 4) {
            float a0[4], a1[4], a2[4], a3[4];
            *(float4*)a0 = *(const float4*)&Ps[(ty*4+0)*68 + c4];
            *(float4*)a1 = *(const float4*)&Ps[(ty*4+1)*68 + c4];
            *(float4*)a2 = *(const float4*)&Ps[(ty*4+2)*68 + c4];
            *(float4*)a3 = *(const float4*)&Ps[(ty*4+3)*68 + c4];
            #pragma unroll
            for (int cc = 0; cc < 4; cc++) {
                float bv[4];
                *(float4*)bv = *(const float4*)&Vs[(c4+cc)*64 + tx*4];
                #pragma unroll
                for (int j = 0; j < 4; j++) {
                    o[0][j] += a0[cc] * bv[j];
                    o[1][j] += a1[cc] * bv[j];
                    o[2][j] += a2[cc] * bv[j];
                    o[3][j] += a3[cc] * bv[j];
                }
            }
        }
    }

    // Normalize and store
    #pragma unroll
    for (int i = 0; i < 4; i++) {
        float inv = 1.0f / l_i[i];
        float4 ov = make_float4(o[i][0]*inv, o[i][1]*inv, o[i][2]*inv, o[i][3]*inv);
        *(float4*)&O[(size_t)(b*SS + s0 + ty*4 + i) * DMD + h*HDD + tx*4] = ov;
    }
}

// ---------------------------------------------------------------------------
// LayerNorm over rows of 768. One block per row.
// ---------------------------------------------------------------------------
__global__ __launch_bounds__(256) void ln_kernel(
    const float* __restrict__ X, const float* __restrict__ gamma,
    const float* __restrict__ beta, float* __restrict__ out)
{
    const int row = blockIdx.x;
    const float* xr = X + (size_t)row * DMD;
    const int t = threadIdx.x;
    float x0 = xr[t], x1 = xr[t + 256], x2 = xr[t + 512];
    float sum = x0 + x1 + x2;
    float sq  = x0*x0 + x1*x1 + x2*x2;
    #pragma unroll
    for (int off = 16; off > 0; off >>= 1) {
        sum += __shfl_xor_sync(0xffffffffu, sum, off);
        sq  += __shfl_xor_sync(0xffffffffu, sq,  off);
    }
    __shared__ float wsum[8], wsq[8];
    __shared__ float s_mean, s_rstd;
    int wid = t >> 5, lane = t & 31;
    if (lane == 0) { wsum[wid] = sum; wsq[wid] = sq; }
    __syncthreads();
    if (t == 0) {
        float ts = 0.f, tq = 0.f;
        #pragma unroll
        for (int i = 0; i < 8; i++) { ts += wsum[i]; tq += wsq[i]; }
        float mean = ts * (1.0f / DMD);
        float var  = tq * (1.0f / DMD) - mean * mean;
        s_mean = mean;
        s_rstd = rsqrtf(var + 1e-12f);
    }
    __syncthreads();
    float mean = s_mean, rstd = s_rstd;
    out[(size_t)row*DMD + t      ] = (x0 - mean)*rstd*gamma[t      ] + beta[t      ];
    out[(size_t)row*DMD + t + 256] = (x1 - mean)*rstd*gamma[t + 256] + beta[t + 256];
    out[(size_t)row*DMD + t + 512] = (x2 - mean)*rstd*gamma[t + 512] + beta[t + 512];
}

// ---------------------------------------------------------------------------
extern "C" void kernel_launch(void* const* d_in, const int* in_sizes, int n_in,
                              void* d_out, int out_size)
{
    const float* hidden = (const float*)d_in[0];
    const float* cosb   = (const float*)d_in[1];
    const float* sinb   = (const float*)d_in[2];
    const float* Wq     = (const float*)d_in[3];
    const float* bq     = (const float*)d_in[4];
    const float* Wk     = (const float*)d_in[5];
    const float* bk     = (const float*)d_in[6];
    const float* Wv     = (const float*)d_in[7];
    const float* bv     = (const float*)d_in[8];
    const float* Wo     = (const float*)d_in[9];
    const float* ln_g   = (const float*)d_in[10];
    const float* ln_b   = (const float*)d_in[11];

    float *qp, *kp, *vp, *ap, *tp;
    cudaGetSymbolAddress((void**)&qp, g_q);
    cudaGetSymbolAddress((void**)&kp, g_k);
    cudaGetSymbolAddress((void**)&vp, g_v);
    cudaGetSymbolAddress((void**)&ap, g_attn);
    cudaGetSymbolAddress((void**)&tp, g_tmp);

    dim3 gemmGrid(DMD/64, MROWS/64);   // (12, 128)

    gemm_xwt<<<gemmGrid, 256>>>(hidden, Wq, bq, nullptr, qp);
    gemm_xwt<<<gemmGrid, 256>>>(hidden, Wk, bk, nullptr, kp);
    gemm_xwt<<<gemmGrid, 256>>>(hidden, Wv, bv, nullptr, vp);

    rope_kernel<<<(BB*SS*NH*32)/256, 256>>>(qp, kp, cosb, sinb);

    cudaFuncSetAttribute(attn_kernel,
                         cudaFuncAttributeMaxDynamicSharedMemorySize, ATTN_SMEM);
    attn_kernel<<<dim3(SS/64, BB*NH), 256, ATTN_SMEM>>>(qp, kp, vp, ap);

    // out-proj + residual into tmp
    gemm_xwt<<<gemmGrid, 256>>>(ap, Wo, nullptr, hidden, tp);

    ln_kernel<<<MROWS, 256>>>(tp, ln_g, ln_b, (float*)d_out);
}

// round 4
// speedup vs baseline: 3.7293x; 3.7293x over previous
#include <cuda_runtime.h>
#include <math.h>
#include <stdint.h>

#define BB 2
#define SS 4096
#define DMD 768
#define NH 12
#define HDD 64
#define MROWS (BB*SS)

// Scratch (static device globals — allocation-free rule)
__device__ float g_q[MROWS*DMD];
__device__ float g_k[MROWS*DMD];
__device__ float g_v[MROWS*DMD];
__device__ float g_attn[MROWS*DMD];
__device__ float g_tmp[MROWS*DMD];

// ---------------------------------------------------------------------------
// TF32 helpers
// ---------------------------------------------------------------------------
__device__ __forceinline__ uint32_t f2tf(float f) {
    uint32_t r;
    asm("cvt.rna.tf32.f32 %0, %1;" : "=r"(r) : "f"(f));
    return r;
}
__device__ __forceinline__ void mma_tf32(float* c, const uint32_t* a,
                                         uint32_t b0, uint32_t b1) {
    asm volatile(
        "mma.sync.aligned.m16n8k8.row.col.f32.tf32.tf32.f32 "
        "{%0,%1,%2,%3}, {%4,%5,%6,%7}, {%8,%9}, {%0,%1,%2,%3};"
        : "+f"(c[0]), "+f"(c[1]), "+f"(c[2]), "+f"(c[3])
        : "r"(a[0]), "r"(a[1]), "r"(a[2]), "r"(a[3]), "r"(b0), "r"(b1));
}
__device__ __forceinline__ uint32_t fbits(float f) { return __float_as_uint(f); }

// ---------------------------------------------------------------------------
// TF32 GEMM: out[M,N] = X[M,K] @ W[N,K]^T (+bias) (+residual)
// M=8192, N=K=768. Tile 128x64, BK=32, 8 warps (4m x 2n), warp tile 32x32.
// ---------------------------------------------------------------------------
#define GPAD 36
__global__ __launch_bounds__(256) void gemm_mma(
    const float* __restrict__ X, const float* __restrict__ W,
    const float* __restrict__ bias, const float* __restrict__ residual,
    float* __restrict__ out)
{
    __shared__ float As[128 * GPAD];
    __shared__ float Bs[64 * GPAD];

    const int tid  = threadIdx.x;
    const int warp = tid >> 5;
    const int lane = tid & 31;
    const int g    = lane >> 2;
    const int t    = lane & 3;
    const int wm   = warp & 3;      // 0..3 -> 32-row slab
    const int wn   = warp >> 2;     // 0..1 -> 32-col slab
    const int row0 = blockIdx.y * 128;
    const int col0 = blockIdx.x * 64;

    float c[2][4][4] = {};

    for (int k0 = 0; k0 < DMD; k0 += 32) {
        __syncthreads();
        // A tile: 128x32 (4 float4 per thread), convert to tf32 bits
        #pragma unroll
        for (int it = 0; it < 4; it++) {
            int i  = tid + it * 256;
            int r  = i >> 3;
            int kc = (i & 7) * 4;
            float4 v = *(const float4*)&X[(size_t)(row0 + r) * DMD + k0 + kc];
            float4 w;
            w.x = __uint_as_float(f2tf(v.x)); w.y = __uint_as_float(f2tf(v.y));
            w.z = __uint_as_float(f2tf(v.z)); w.w = __uint_as_float(f2tf(v.w));
            *(float4*)&As[r * GPAD + kc] = w;
        }
        // B tile: 64x32 (2 float4 per thread)
        #pragma unroll
        for (int it = 0; it < 2; it++) {
            int i  = tid + it * 256;
            int r  = i >> 3;
            int kc = (i & 7) * 4;
            float4 v = *(const float4*)&W[(size_t)(col0 + r) * DMD + k0 + kc];
            float4 w;
            w.x = __uint_as_float(f2tf(v.x)); w.y = __uint_as_float(f2tf(v.y));
            w.z = __uint_as_float(f2tf(v.z)); w.w = __uint_as_float(f2tf(v.w));
            *(float4*)&Bs[r * GPAD + kc] = w;
        }
        __syncthreads();

        #pragma unroll
        for (int kt = 0; kt < 4; kt++) {
            uint32_t a[2][4];
            #pragma unroll
            for (int mt = 0; mt < 2; mt++) {
                int rm = wm * 32 + mt * 16;
                a[mt][0] = fbits(As[(rm + g    ) * GPAD + kt * 8 + t    ]);
                a[mt][1] = fbits(As[(rm + g + 8) * GPAD + kt * 8 + t    ]);
                a[mt][2] = fbits(As[(rm + g    ) * GPAD + kt * 8 + t + 4]);
                a[mt][3] = fbits(As[(rm + g + 8) * GPAD + kt * 8 + t + 4]);
            }
            #pragma unroll
            for (int nt = 0; nt < 4; nt++) {
                int nb = wn * 32 + nt * 8;
                uint32_t b0 = fbits(Bs[(nb + g) * GPAD + kt * 8 + t    ]);
                uint32_t b1 = fbits(Bs[(nb + g) * GPAD + kt * 8 + t + 4]);
                mma_tf32(c[0][nt], a[0], b0, b1);
                mma_tf32(c[1][nt], a[1], b0, b1);
            }
        }
    }

    // Epilogue
    #pragma unroll
    for (int mt = 0; mt < 2; mt++) {
        #pragma unroll
        for (int nt = 0; nt < 4; nt++) {
            int r0 = row0 + wm * 32 + mt * 16 + g;
            int cc = col0 + wn * 32 + nt * 8 + 2 * t;
            float v0 = c[mt][nt][0], v1 = c[mt][nt][1];
            float v2 = c[mt][nt][2], v3 = c[mt][nt][3];
            if (bias) {
                float b0 = bias[cc], b1 = bias[cc + 1];
                v0 += b0; v1 += b1; v2 += b0; v3 += b1;
            }
            if (residual) {
                v0 += residual[(size_t)r0 * DMD + cc];
                v1 += residual[(size_t)r0 * DMD + cc + 1];
                v2 += residual[(size_t)(r0 + 8) * DMD + cc];
                v3 += residual[(size_t)(r0 + 8) * DMD + cc + 1];
            }
            *(float2*)&out[(size_t)r0 * DMD + cc]       = make_float2(v0, v1);
            *(float2*)&out[(size_t)(r0 + 8) * DMD + cc] = make_float2(v2, v3);
        }
    }
}

// ---------------------------------------------------------------------------
// RoPE (in-place) on q and k. q additionally scaled by 1/HD (both SCALINGs).
// ---------------------------------------------------------------------------
__global__ __launch_bounds__(256) void rope_kernel(
    float* __restrict__ q, float* __restrict__ k,
    const float* __restrict__ cosb, const float* __restrict__ sinb)
{
    int idx = blockIdx.x * blockDim.x + threadIdx.x;
    int d = idx & 31;
    int h = (idx >> 5) % NH;
    int s = (idx >> 5) / NH % SS;
    int b = idx / (32 * NH * SS);
    size_t base = ((size_t)(b * SS + s)) * DMD + h * HDD;
    float c1 = cosb[s*HDD + d],      s1 = sinb[s*HDD + d];
    float c2 = cosb[s*HDD + d + 32], s2 = sinb[s*HDD + d + 32];

    const float qs = 1.0f / (float)HDD;
    float q1 = q[base + d], q2 = q[base + d + 32];
    q[base + d]      = (q1*c1 - q2*s1) * qs;
    q[base + d + 32] = (q2*c2 + q1*s2) * qs;

    float k1 = k[base + d], k2 = k[base + d + 32];
    k[base + d]      = k1*c1 - k2*s1;
    k[base + d + 32] = k2*c2 + k1*s2;
}

// ---------------------------------------------------------------------------
// Flash attention with TF32 MMA.
// Block: 128 q-rows, 8 warps (each warp owns 16 rows). KV tiles of 64.
// Smem strides: QPs/Ks stride 68 (bank=4g+t conflict-free), Vs stride 72
// (bank=8t+g conflict-free).
// ---------------------------------------------------------------------------
#define QP_STRIDE 68
#define V_STRIDE  72
#define ATTN_SMEM ((128*QP_STRIDE + 64*QP_STRIDE + 64*V_STRIDE) * 4)

__global__ __launch_bounds__(256) void attn_mma(
    const float* __restrict__ Q, const float* __restrict__ K,
    const float* __restrict__ V, float* __restrict__ O)
{
    extern __shared__ float sm[];
    float* QPs = sm;                          // 128 x 68 (Q tile, then P tile)
    float* Ks  = sm + 128 * QP_STRIDE;        // 64 x 68 (tf32 bits)
    float* Vs  = Ks + 64 * QP_STRIDE;         // 64 x 72 (tf32 bits)

    const int tid  = threadIdx.x;
    const int warp = tid >> 5;
    const int lane = tid & 31;
    const int g    = lane >> 2;
    const int t    = lane & 3;
    const int rm   = warp * 16;               // warp's row base within tile
    const int bh   = blockIdx.y;
    const int b    = bh / NH, h = bh % NH;
    const int s0   = blockIdx.x * 128;

    const float* Qb = Q + (size_t)b * SS * DMD + h * HDD;
    const float* Kb = K + (size_t)b * SS * DMD + h * HDD;
    const float* Vb = V + (size_t)b * SS * DMD + h * HDD;

    // Load Q tile (128x64) cooperatively
    #pragma unroll
    for (int it = 0; it < 8; it++) {
        int i  = tid + it * 256;
        int r  = i >> 4;
        int c4 = (i & 15) * 4;
        float4 v = *(const float4*)&Qb[(size_t)(s0 + r) * DMD + c4];
        *(float4*)&QPs[r * QP_STRIDE + c4] = v;
    }
    __syncthreads();

    // Q fragments (persistent, tf32)
    uint32_t qa[8][4];
    #pragma unroll
    for (int kt = 0; kt < 8; kt++) {
        qa[kt][0] = f2tf(QPs[(rm + g    ) * QP_STRIDE + kt * 8 + t    ]);
        qa[kt][1] = f2tf(QPs[(rm + g + 8) * QP_STRIDE + kt * 8 + t    ]);
        qa[kt][2] = f2tf(QPs[(rm + g    ) * QP_STRIDE + kt * 8 + t + 4]);
        qa[kt][3] = f2tf(QPs[(rm + g + 8) * QP_STRIDE + kt * 8 + t + 4]);
    }

    float o[8][4] = {};
    float m0 = -1e30f, m1 = -1e30f, l0 = 0.0f, l1 = 0.0f;

    for (int t0 = 0; t0 < SS; t0 += 64) {
        __syncthreads();   // prior tile's Ks/Vs fully consumed
        // Load K/V tiles (64x64 each), convert to tf32 bits
        #pragma unroll
        for (int it = 0; it < 4; it++) {
            int i  = tid + it * 256;
            int r  = i >> 4;
            int c4 = (i & 15) * 4;
            float4 kv = *(const float4*)&Kb[(size_t)(t0 + r) * DMD + c4];
            float4 kw;
            kw.x = __uint_as_float(f2tf(kv.x)); kw.y = __uint_as_float(f2tf(kv.y));
            kw.z = __uint_as_float(f2tf(kv.z)); kw.w = __uint_as_float(f2tf(kv.w));
            *(float4*)&Ks[r * QP_STRIDE + c4] = kw;
            float4 vv = *(const float4*)&Vb[(size_t)(t0 + r) * DMD + c4];
            float4 vw;
            vw.x = __uint_as_float(f2tf(vv.x)); vw.y = __uint_as_float(f2tf(vv.y));
            vw.z = __uint_as_float(f2tf(vv.z)); vw.w = __uint_as_float(f2tf(vv.w));
            *(float4*)&Vs[r * V_STRIDE + c4] = vw;
        }
        __syncthreads();

        // S = Q K^T  (q already carries 1/HD)
        float s[8][4] = {};
        #pragma unroll
        for (int nt = 0; nt < 8; nt++) {
            #pragma unroll
            for (int kt = 0; kt < 8; kt++) {
                uint32_t b0 = fbits(Ks[(nt * 8 + g) * QP_STRIDE + kt * 8 + t    ]);
                uint32_t b1 = fbits(Ks[(nt * 8 + g) * QP_STRIDE + kt * 8 + t + 4]);
                mma_tf32(s[nt], qa[kt], b0, b1);
            }
        }

        // Online softmax. Rows: rm+g (regs 0,1), rm+g+8 (regs 2,3).
        float mx0 = -1e30f, mx1 = -1e30f;
        #pragma unroll
        for (int nt = 0; nt < 8; nt++) {
            mx0 = fmaxf(mx0, fmaxf(s[nt][0], s[nt][1]));
            mx1 = fmaxf(mx1, fmaxf(s[nt][2], s[nt][3]));
        }
        mx0 = fmaxf(mx0, __shfl_xor_sync(0xffffffffu, mx0, 1));
        mx0 = fmaxf(mx0, __shfl_xor_sync(0xffffffffu, mx0, 2));
        mx1 = fmaxf(mx1, __shfl_xor_sync(0xffffffffu, mx1, 1));
        mx1 = fmaxf(mx1, __shfl_xor_sync(0xffffffffu, mx1, 2));

        float nm0 = fmaxf(m0, mx0), nm1 = fmaxf(m1, mx1);
        float fc0 = __expf(m0 - nm0), fc1 = __expf(m1 - nm1);
        float sum0 = 0.0f, sum1 = 0.0f;
        #pragma unroll
        for (int nt = 0; nt < 8; nt++) {
            s[nt][0] = __expf(s[nt][0] - nm0);
            s[nt][1] = __expf(s[nt][1] - nm0);
            s[nt][2] = __expf(s[nt][2] - nm1);
            s[nt][3] = __expf(s[nt][3] - nm1);
            sum0 += s[nt][0] + s[nt][1];
            sum1 += s[nt][2] + s[nt][3];
        }
        sum0 += __shfl_xor_sync(0xffffffffu, sum0, 1);
        sum0 += __shfl_xor_sync(0xffffffffu, sum0, 2);
        sum1 += __shfl_xor_sync(0xffffffffu, sum1, 1);
        sum1 += __shfl_xor_sync(0xffffffffu, sum1, 2);
        l0 = l0 * fc0 + sum0;  m0 = nm0;
        l1 = l1 * fc1 + sum1;  m1 = nm1;
        #pragma unroll
        for (int nt = 0; nt < 8; nt++) {
            o[nt][0] *= fc0; o[nt][1] *= fc0;
            o[nt][2] *= fc1; o[nt][3] *= fc1;
        }

        // Store P (tf32 bits) into warp-private rows of QPs
        #pragma unroll
        for (int nt = 0; nt < 8; nt++) {
            float2 p01 = make_float2(__uint_as_float(f2tf(s[nt][0])),
                                     __uint_as_float(f2tf(s[nt][1])));
            float2 p23 = make_float2(__uint_as_float(f2tf(s[nt][2])),
                                     __uint_as_float(f2tf(s[nt][3])));
            *(float2*)&QPs[(rm + g    ) * QP_STRIDE + nt * 8 + 2 * t] = p01;
            *(float2*)&QPs[(rm + g + 8) * QP_STRIDE + nt * 8 + 2 * t] = p23;
        }
        __syncwarp();

        // P fragments
        uint32_t pa[8][4];
        #pragma unroll
        for (int kt = 0; kt < 8; kt++) {
            pa[kt][0] = fbits(QPs[(rm + g    ) * QP_STRIDE + kt * 8 + t    ]);
            pa[kt][1] = fbits(QPs[(rm + g + 8) * QP_STRIDE + kt * 8 + t    ]);
            pa[kt][2] = fbits(QPs[(rm + g    ) * QP_STRIDE + kt * 8 + t + 4]);
            pa[kt][3] = fbits(QPs[(rm + g + 8) * QP_STRIDE + kt * 8 + t + 4]);
        }

        // O += P V
        #pragma unroll
        for (int nt = 0; nt < 8; nt++) {
            #pragma unroll
            for (int kt = 0; kt < 8; kt++) {
                uint32_t b0 = fbits(Vs[(kt * 8 + t    ) * V_STRIDE + nt * 8 + g]);
                uint32_t b1 = fbits(Vs[(kt * 8 + t + 4) * V_STRIDE + nt * 8 + g]);
                mma_tf32(o[nt], pa[kt], b0, b1);
            }
        }
    }

    // Normalize and store O
    float inv0 = 1.0f / l0, inv1 = 1.0f / l1;
    float* Ob = O + (size_t)b * SS * DMD + h * HDD;
    #pragma unroll
    for (int nt = 0; nt < 8; nt++) {
        int cc = nt * 8 + 2 * t;
        *(float2*)&Ob[(size_t)(s0 + rm + g) * DMD + cc] =
            make_float2(o[nt][0] * inv0, o[nt][1] * inv0);
        *(float2*)&Ob[(size_t)(s0 + rm + g + 8) * DMD + cc] =
            make_float2(o[nt][2] * inv1, o[nt][3] * inv1);
    }
}

// ---------------------------------------------------------------------------
// LayerNorm over rows of 768. One block per row.
// ---------------------------------------------------------------------------
__global__ __launch_bounds__(256) void ln_kernel(
    const float* __restrict__ X, const float* __restrict__ gamma,
    const float* __restrict__ beta, float* __restrict__ out)
{
    const int row = blockIdx.x;
    const float* xr = X + (size_t)row * DMD;
    const int t = threadIdx.x;
    float x0 = xr[t], x1 = xr[t + 256], x2 = xr[t + 512];
    float sum = x0 + x1 + x2;
    float sq  = x0*x0 + x1*x1 + x2*x2;
    #pragma unroll
    for (int off = 16; off > 0; off >>= 1) {
        sum += __shfl_xor_sync(0xffffffffu, sum, off);
        sq  += __shfl_xor_sync(0xffffffffu, sq,  off);
    }
    __shared__ float wsum[8], wsq[8];
    __shared__ float s_mean, s_rstd;
    int wid = t >> 5, lane = t & 31;
    if (lane == 0) { wsum[wid] = sum; wsq[wid] = sq; }
    __syncthreads();
    if (t == 0) {
        float ts = 0.f, tq = 0.f;
        #pragma unroll
        for (int i = 0; i < 8; i++) { ts += wsum[i]; tq += wsq[i]; }
        float mean = ts * (1.0f / DMD);
        float var  = tq * (1.0f / DMD) - mean * mean;
        s_mean = mean;
        s_rstd = rsqrtf(var + 1e-12f);
    }
    __syncthreads();
    float mean = s_mean, rstd = s_rstd;
    out[(size_t)row*DMD + t      ] = (x0 - mean)*rstd*gamma[t      ] + beta[t      ];
    out[(size_t)row*DMD + t + 256] = (x1 - mean)*rstd*gamma[t + 256] + beta[t + 256];
    out[(size_t)row*DMD + t + 512] = (x2 - mean)*rstd*gamma[t + 512] + beta[t + 512];
}

// ---------------------------------------------------------------------------
extern "C" void kernel_launch(void* const* d_in, const int* in_sizes, int n_in,
                              void* d_out, int out_size)
{
    const float* hidden = (const float*)d_in[0];
    const float* cosb   = (const float*)d_in[1];
    const float* sinb   = (const float*)d_in[2];
    const float* Wq     = (const float*)d_in[3];
    const float* bq     = (const float*)d_in[4];
    const float* Wk     = (const float*)d_in[5];
    const float* bk     = (const float*)d_in[6];
    const float* Wv     = (const float*)d_in[7];
    const float* bv     = (const float*)d_in[8];
    const float* Wo     = (const float*)d_in[9];
    const float* ln_g   = (const float*)d_in[10];
    const float* ln_b   = (const float*)d_in[11];

    float *qp, *kp, *vp, *ap, *tp;
    cudaGetSymbolAddress((void**)&qp, g_q);
    cudaGetSymbolAddress((void**)&kp, g_k);
    cudaGetSymbolAddress((void**)&vp, g_v);
    cudaGetSymbolAddress((void**)&ap, g_attn);
    cudaGetSymbolAddress((void**)&tp, g_tmp);

    dim3 gemmGrid(DMD/64, MROWS/128);   // (12, 64)

    gemm_mma<<<gemmGrid, 256>>>(hidden, Wq, bq, nullptr, qp);
    gemm_mma<<<gemmGrid, 256>>>(hidden, Wk, bk, nullptr, kp);
    gemm_mma<<<gemmGrid, 256>>>(hidden, Wv, bv, nullptr, vp);

    rope_kernel<<<(BB*SS*NH*32)/256, 256>>>(qp, kp, cosb, sinb);

    cudaFuncSetAttribute(attn_mma,
                         cudaFuncAttributeMaxDynamicSharedMemorySize, ATTN_SMEM);
    attn_mma<<<dim3(SS/128, BB*NH), 256, ATTN_SMEM>>>(qp, kp, vp, ap);

    // out-proj + residual into tmp
    gemm_mma<<<gemmGrid, 256>>>(ap, Wo, nullptr, hidden, tp);

    ln_kernel<<<MROWS, 256>>>(tp, ln_g, ln_b, (float*)d_out);
}

// round 5
// speedup vs baseline: 4.5885x; 1.2304x over previous
#include <cuda_runtime.h>
#include <cuda_bf16.h>
#include <math.h>
#include <stdint.h>

#define BB 2
#define SS 4096
#define DMD 768
#define NH 12
#define HDD 64
#define MROWS (BB*SS)

// Scratch (static device globals — allocation-free rule)
__device__ __nv_bfloat16 g_q[MROWS*DMD];
__device__ __nv_bfloat16 g_k[MROWS*DMD];
__device__ __nv_bfloat16 g_v[MROWS*DMD];
__device__ __nv_bfloat16 g_attn[MROWS*DMD];
__device__ float         g_tmp[MROWS*DMD];

// ---------------------------------------------------------------------------
// Helpers
// ---------------------------------------------------------------------------
__device__ __forceinline__ uint32_t packbf(float a, float b) {
    __nv_bfloat162 h = __floats2bfloat162_rn(a, b);   // x=a (low), y=b (high)
    return *(uint32_t*)&h;
}
__device__ __forceinline__ void mma_bf16(float* c, const uint32_t* a,
                                         uint32_t b0, uint32_t b1) {
    asm volatile(
        "mma.sync.aligned.m16n8k16.row.col.f32.bf16.bf16.f32 "
        "{%0,%1,%2,%3}, {%4,%5,%6,%7}, {%8,%9}, {%0,%1,%2,%3};"
        : "+f"(c[0]), "+f"(c[1]), "+f"(c[2]), "+f"(c[3])
        : "r"(a[0]), "r"(a[1]), "r"(a[2]), "r"(a[3]), "r"(b0), "r"(b1));
}

// ---------------------------------------------------------------------------
// bf16 GEMM: out[M,N] = X[M,K] @ W[N,K]^T (+bias) (+residual)
// M=8192, N=K=768. Tile 128x64, BK=32, 8 warps (4m x 2n), warp tile 32x32.
// Smem tiles bf16, row stride 40 halves (20 words) -> frag LDS bank 20g+t
// (conflict-free).
// ---------------------------------------------------------------------------
#define GSW 20   // stride in 32-bit words (= 40 halves)

template<typename Tin, bool OUT_BF16>
__global__ __launch_bounds__(256) void gemm_bf16(
    const Tin* __restrict__ X, const float* __restrict__ W,
    const float* __restrict__ bias, const float* __restrict__ residual,
    void* __restrict__ outv)
{
    __shared__ uint32_t As[128 * GSW];
    __shared__ uint32_t Bs[64 * GSW];

    const int tid  = threadIdx.x;
    const int warp = tid >> 5;
    const int lane = tid & 31;
    const int g    = lane >> 2;
    const int t    = lane & 3;
    const int wm   = warp & 3;
    const int wn   = warp >> 2;
    const int row0 = blockIdx.y * 128;
    const int col0 = blockIdx.x * 64;

    float c[2][4][4] = {};

    for (int k0 = 0; k0 < DMD; k0 += 32) {
        __syncthreads();
        // A tile 128x32 -> bf16. Each thread: one row-chunk of 8 halves, 2 iters.
        #pragma unroll
        for (int it = 0; it < 2; it++) {
            int i  = tid + it * 256;          // 0..511
            int r  = i >> 2;                  // 0..127
            int c8 = (i & 3) * 8;             // 0,8,16,24
            uint4 dst;
            if constexpr (!OUT_BF16 || true) {} // (silence unused warnings)
            if constexpr (sizeof(Tin) == 4) {
                const float* src = (const float*)X + (size_t)(row0 + r) * DMD + k0 + c8;
                float4 v0 = *(const float4*)src;
                float4 v1 = *(const float4*)(src + 4);
                dst.x = packbf(v0.x, v0.y); dst.y = packbf(v0.z, v0.w);
                dst.z = packbf(v1.x, v1.y); dst.w = packbf(v1.z, v1.w);
            } else {
                dst = *(const uint4*)((const __nv_bfloat16*)X +
                        (size_t)(row0 + r) * DMD + k0 + c8);
            }
            *(uint4*)&As[r * GSW + c8 / 2] = dst;
        }
        // B tile 64x32 (weights fp32), 1 iter
        {
            int r  = tid >> 2;
            int c8 = (tid & 3) * 8;
            const float* src = W + (size_t)(col0 + r) * DMD + k0 + c8;
            float4 v0 = *(const float4*)src;
            float4 v1 = *(const float4*)(src + 4);
            uint4 dst;
            dst.x = packbf(v0.x, v0.y); dst.y = packbf(v0.z, v0.w);
            dst.z = packbf(v1.x, v1.y); dst.w = packbf(v1.z, v1.w);
            *(uint4*)&Bs[r * GSW + c8 / 2] = dst;
        }
        __syncthreads();

        #pragma unroll
        for (int kt = 0; kt < 2; kt++) {      // two k16 steps
            uint32_t a[2][4];
            #pragma unroll
            for (int mt = 0; mt < 2; mt++) {
                int rm = wm * 32 + mt * 16;
                a[mt][0] = As[(rm + g    ) * GSW + kt * 8 + t    ];
                a[mt][1] = As[(rm + g + 8) * GSW + kt * 8 + t    ];
                a[mt][2] = As[(rm + g    ) * GSW + kt * 8 + t + 4];
                a[mt][3] = As[(rm + g + 8) * GSW + kt * 8 + t + 4];
            }
            #pragma unroll
            for (int nt = 0; nt < 4; nt++) {
                int nb = wn * 32 + nt * 8;
                uint32_t b0 = Bs[(nb + g) * GSW + kt * 8 + t    ];
                uint32_t b1 = Bs[(nb + g) * GSW + kt * 8 + t + 4];
                mma_bf16(c[0][nt], a[0], b0, b1);
                mma_bf16(c[1][nt], a[1], b0, b1);
            }
        }
    }

    // Epilogue
    #pragma unroll
    for (int mt = 0; mt < 2; mt++) {
        #pragma unroll
        for (int nt = 0; nt < 4; nt++) {
            int r0 = row0 + wm * 32 + mt * 16 + g;
            int cc = col0 + wn * 32 + nt * 8 + 2 * t;
            float v0 = c[mt][nt][0], v1 = c[mt][nt][1];
            float v2 = c[mt][nt][2], v3 = c[mt][nt][3];
            if (bias) {
                float b0 = bias[cc], b1 = bias[cc + 1];
                v0 += b0; v1 += b1; v2 += b0; v3 += b1;
            }
            if (residual) {
                v0 += residual[(size_t)r0 * DMD + cc];
                v1 += residual[(size_t)r0 * DMD + cc + 1];
                v2 += residual[(size_t)(r0 + 8) * DMD + cc];
                v3 += residual[(size_t)(r0 + 8) * DMD + cc + 1];
            }
            if constexpr (OUT_BF16) {
                __nv_bfloat16* out = (__nv_bfloat16*)outv;
                *(uint32_t*)&out[(size_t)r0 * DMD + cc]       = packbf(v0, v1);
                *(uint32_t*)&out[(size_t)(r0 + 8) * DMD + cc] = packbf(v2, v3);
            } else {
                float* out = (float*)outv;
                *(float2*)&out[(size_t)r0 * DMD + cc]       = make_float2(v0, v1);
                *(float2*)&out[(size_t)(r0 + 8) * DMD + cc] = make_float2(v2, v3);
            }
        }
    }
}

// ---------------------------------------------------------------------------
// RoPE (in-place, bf16). q additionally scaled by 1/HD (both SCALINGs).
// ---------------------------------------------------------------------------
__global__ __launch_bounds__(256) void rope_kernel(
    __nv_bfloat16* __restrict__ q, __nv_bfloat16* __restrict__ k,
    const float* __restrict__ cosb, const float* __restrict__ sinb)
{
    int idx = blockIdx.x * blockDim.x + threadIdx.x;
    int d = idx & 31;
    int h = (idx >> 5) % NH;
    int s = (idx >> 5) / NH % SS;
    int b = idx / (32 * NH * SS);
    size_t base = ((size_t)(b * SS + s)) * DMD + h * HDD;
    float c1 = cosb[s*HDD + d],      s1 = sinb[s*HDD + d];
    float c2 = cosb[s*HDD + d + 32], s2 = sinb[s*HDD + d + 32];

    const float qs = 1.0f / (float)HDD;
    float q1 = __bfloat162float(q[base + d]);
    float q2 = __bfloat162float(q[base + d + 32]);
    q[base + d]      = __float2bfloat16((q1*c1 - q2*s1) * qs);
    q[base + d + 32] = __float2bfloat16((q2*c2 + q1*s2) * qs);

    float k1 = __bfloat162float(k[base + d]);
    float k2 = __bfloat162float(k[base + d + 32]);
    k[base + d]      = __float2bfloat16(k1*c1 - k2*s1);
    k[base + d + 32] = __float2bfloat16(k2*c2 + k1*s2);
}

// ---------------------------------------------------------------------------
// Flash attention, bf16 MMA (m16n8k16).
// Block: 128 q-rows, 8 warps (16 rows each). KV tiles of 64 keys.
// QP smem (Q tile, then P tile): 128 rows x 40 halves (20 words) - bank 20g+t.
// K smem: 64 x 40 halves. Vt smem (transposed V): 64 d-rows x 72 halves
// (36 words) - bank 4g+t. All conflict-free for both fill and frag reads.
// ---------------------------------------------------------------------------
#define VSW 36   // Vt stride in words

__global__ __launch_bounds__(256) void attn_mma(
    const __nv_bfloat16* __restrict__ Q, const __nv_bfloat16* __restrict__ K,
    const __nv_bfloat16* __restrict__ V, __nv_bfloat16* __restrict__ O)
{
    __shared__ uint32_t QPs[128 * GSW];   // 10.2 KB
    __shared__ uint32_t Ks [64 * GSW];    // 5.1 KB
    __shared__ uint32_t Vts[64 * VSW];    // 9.2 KB

    const int tid  = threadIdx.x;
    const int warp = tid >> 5;
    const int lane = tid & 31;
    const int g    = lane >> 2;
    const int t    = lane & 3;
    const int rm   = warp * 16;
    const int bh   = blockIdx.y;
    const int b    = bh / NH, h = bh % NH;
    const int s0   = blockIdx.x * 128;

    const __nv_bfloat16* Qb = Q + (size_t)b * SS * DMD + h * HDD;
    const __nv_bfloat16* Kb = K + (size_t)b * SS * DMD + h * HDD;
    const __nv_bfloat16* Vb = V + (size_t)b * SS * DMD + h * HDD;

    // Stage Q tile (128 x 64 halves)
    #pragma unroll
    for (int it = 0; it < 4; it++) {
        int i  = tid + it * 256;          // 0..1023
        int r  = i >> 3;                  // 0..127
        int c8 = (i & 7) * 8;             // 0..56
        uint4 v = *(const uint4*)&Qb[(size_t)(s0 + r) * DMD + c8];
        *(uint4*)&QPs[r * GSW + c8 / 2] = v;
    }
    __syncthreads();

    // Persistent Q fragments: qa[kt][0..3], kt over 4 k16 blocks (d=64)
    uint32_t qa[4][4];
    #pragma unroll
    for (int kt = 0; kt < 4; kt++) {
        qa[kt][0] = QPs[(rm + g    ) * GSW + kt * 8 + t    ];
        qa[kt][1] = QPs[(rm + g + 8) * GSW + kt * 8 + t    ];
        qa[kt][2] = QPs[(rm + g    ) * GSW + kt * 8 + t + 4];
        qa[kt][3] = QPs[(rm + g + 8) * GSW + kt * 8 + t + 4];
    }

    float o[8][4] = {};
    float m0 = -1e30f, m1 = -1e30f, l0 = 0.0f, l1 = 0.0f;

    for (int t0 = 0; t0 < SS; t0 += 64) {
        __syncthreads();   // prior tile's Ks/Vts fully consumed
        // K tile: 64 keys x 64 d halves, straight copy (2 iters)
        #pragma unroll
        for (int it = 0; it < 2; it++) {
            int i  = tid + it * 256;      // 0..511
            int r  = i >> 3;              // 0..63
            int c8 = (i & 7) * 8;
            uint4 v = *(const uint4*)&Kb[(size_t)(t0 + r) * DMD + c8];
            *(uint4*)&Ks[r * GSW + c8 / 2] = v;
        }
        // V tile transposed: thread -> key pair (2p,2p+1), 8 d values.
        {
            int pair = tid & 31;              // 0..31 -> keys 2p, 2p+1
            int d8   = (tid >> 5) * 8;        // 0..56
            const ushort4* va = (const ushort4*)&Vb[(size_t)(t0 + 2*pair    ) * DMD + d8];
            const ushort4* vb = (const ushort4*)&Vb[(size_t)(t0 + 2*pair + 1) * DMD + d8];
            ushort4 a0 = va[0], a1 = va[1];
            ushort4 b0 = vb[0], b1 = vb[1];
            const unsigned short* ah = (const unsigned short*)&a0;
            const unsigned short* bh = (const unsigned short*)&b0;
            #pragma unroll
            for (int j = 0; j < 4; j++)
                Vts[(d8 + j) * VSW + pair] = (uint32_t)ah[j] | ((uint32_t)bh[j] << 16);
            const unsigned short* ah2 = (const unsigned short*)&a1;
            const unsigned short* bh2 = (const unsigned short*)&b1;
            #pragma unroll
            for (int j = 0; j < 4; j++)
                Vts[(d8 + 4 + j) * VSW + pair] = (uint32_t)ah2[j] | ((uint32_t)bh2[j] << 16);
        }
        __syncthreads();

        // S = Q K^T  (q already carries 1/HD)
        float s[8][4] = {};
        #pragma unroll
        for (int nt = 0; nt < 8; nt++) {
            #pragma unroll
            for (int kt = 0; kt < 4; kt++) {
                uint32_t b0 = Ks[(nt * 8 + g) * GSW + kt * 8 + t    ];
                uint32_t b1 = Ks[(nt * 8 + g) * GSW + kt * 8 + t + 4];
                mma_bf16(s[nt], qa[kt], b0, b1);
            }
        }

        // Online softmax. Rows rm+g (regs 0,1) and rm+g+8 (regs 2,3).
        float mx0 = -1e30f, mx1 = -1e30f;
        #pragma unroll
        for (int nt = 0; nt < 8; nt++) {
            mx0 = fmaxf(mx0, fmaxf(s[nt][0], s[nt][1]));
            mx1 = fmaxf(mx1, fmaxf(s[nt][2], s[nt][3]));
        }
        mx0 = fmaxf(mx0, __shfl_xor_sync(0xffffffffu, mx0, 1));
        mx0 = fmaxf(mx0, __shfl_xor_sync(0xffffffffu, mx0, 2));
        mx1 = fmaxf(mx1, __shfl_xor_sync(0xffffffffu, mx1, 1));
        mx1 = fmaxf(mx1, __shfl_xor_sync(0xffffffffu, mx1, 2));

        float nm0 = fmaxf(m0, mx0), nm1 = fmaxf(m1, mx1);
        float fc0 = __expf(m0 - nm0), fc1 = __expf(m1 - nm1);
        float sum0 = 0.0f, sum1 = 0.0f;
        #pragma unroll
        for (int nt = 0; nt < 8; nt++) {
            s[nt][0] = __expf(s[nt][0] - nm0);
            s[nt][1] = __expf(s[nt][1] - nm0);
            s[nt][2] = __expf(s[nt][2] - nm1);
            s[nt][3] = __expf(s[nt][3] - nm1);
            sum0 += s[nt][0] + s[nt][1];
            sum1 += s[nt][2] + s[nt][3];
        }
        sum0 += __shfl_xor_sync(0xffffffffu, sum0, 1);
        sum0 += __shfl_xor_sync(0xffffffffu, sum0, 2);
        sum1 += __shfl_xor_sync(0xffffffffu, sum1, 1);
        sum1 += __shfl_xor_sync(0xffffffffu, sum1, 2);
        l0 = l0 * fc0 + sum0;  m0 = nm0;
        l1 = l1 * fc1 + sum1;  m1 = nm1;
        #pragma unroll
        for (int nt = 0; nt < 8; nt++) {
            o[nt][0] *= fc0; o[nt][1] *= fc0;
            o[nt][2] *= fc1; o[nt][3] *= fc1;
        }

        // P (bf16) into warp-private rows of QPs
        #pragma unroll
        for (int nt = 0; nt < 8; nt++) {
            QPs[(rm + g    ) * GSW + nt * 4 + t] = packbf(s[nt][0], s[nt][1]);
            QPs[(rm + g + 8) * GSW + nt * 4 + t] = packbf(s[nt][2], s[nt][3]);
        }
        __syncwarp();

        // P fragments (k = 64 keys -> 4 k16 blocks)
        uint32_t pa[4][4];
        #pragma unroll
        for (int kt = 0; kt < 4; kt++) {
            pa[kt][0] = QPs[(rm + g    ) * GSW + kt * 8 + t    ];
            pa[kt][1] = QPs[(rm + g + 8) * GSW + kt * 8 + t    ];
            pa[kt][2] = QPs[(rm + g    ) * GSW + kt * 8 + t + 4];
            pa[kt][3] = QPs[(rm + g + 8) * GSW + kt * 8 + t + 4];
        }

        // O += P V   (B frags from transposed V)
        #pragma unroll
        for (int nt = 0; nt < 8; nt++) {
            #pragma unroll
            for (int kt = 0; kt < 4; kt++) {
                uint32_t b0 = Vts[(nt * 8 + g) * VSW + kt * 8 + t    ];
                uint32_t b1 = Vts[(nt * 8 + g) * VSW + kt * 8 + t + 4];
                mma_bf16(o[nt], pa[kt], b0, b1);
            }
        }
    }

    // Normalize and store O (bf16)
    float inv0 = 1.0f / l0, inv1 = 1.0f / l1;
    __nv_bfloat16* Ob = O + (size_t)b * SS * DMD + h * HDD;
    #pragma unroll
    for (int nt = 0; nt < 8; nt++) {
        int cc = nt * 8 + 2 * t;
        *(uint32_t*)&Ob[(size_t)(s0 + rm + g) * DMD + cc] =
            packbf(o[nt][0] * inv0, o[nt][1] * inv0);
        *(uint32_t*)&Ob[(size_t)(s0 + rm + g + 8) * DMD + cc] =
            packbf(o[nt][2] * inv1, o[nt][3] * inv1);
    }
}

// ---------------------------------------------------------------------------
// LayerNorm over rows of 768. One block per row.
// ---------------------------------------------------------------------------
__global__ __launch_bounds__(256) void ln_kernel(
    const float* __restrict__ X, const float* __restrict__ gamma,
    const float* __restrict__ beta, float* __restrict__ out)
{
    const int row = blockIdx.x;
    const float* xr = X + (size_t)row * DMD;
    const int t = threadIdx.x;
    float x0 = xr[t], x1 = xr[t + 256], x2 = xr[t + 512];
    float sum = x0 + x1 + x2;
    float sq  = x0*x0 + x1*x1 + x2*x2;
    #pragma unroll
    for (int off = 16; off > 0; off >>= 1) {
        sum += __shfl_xor_sync(0xffffffffu, sum, off);
        sq  += __shfl_xor_sync(0xffffffffu, sq,  off);
    }
    __shared__ float wsum[8], wsq[8];
    __shared__ float s_mean, s_rstd;
    int wid = t >> 5, lane = t & 31;
    if (lane == 0) { wsum[wid] = sum; wsq[wid] = sq; }
    __syncthreads();
    if (t == 0) {
        float ts = 0.f, tq = 0.f;
        #pragma unroll
        for (int i = 0; i < 8; i++) { ts += wsum[i]; tq += wsq[i]; }
        float mean = ts * (1.0f / DMD);
        float var  = tq * (1.0f / DMD) - mean * mean;
        s_mean = mean;
        s_rstd = rsqrtf(var + 1e-12f);
    }
    __syncthreads();
    float mean = s_mean, rstd = s_rstd;
    out[(size_t)row*DMD + t      ] = (x0 - mean)*rstd*gamma[t      ] + beta[t      ];
    out[(size_t)row*DMD + t + 256] = (x1 - mean)*rstd*gamma[t + 256] + beta[t + 256];
    out[(size_t)row*DMD + t + 512] = (x2 - mean)*rstd*gamma[t + 512] + beta[t + 512];
}

// ---------------------------------------------------------------------------
extern "C" void kernel_launch(void* const* d_in, const int* in_sizes, int n_in,
                              void* d_out, int out_size)
{
    const float* hidden = (const float*)d_in[0];
    const float* cosb   = (const float*)d_in[1];
    const float* sinb   = (const float*)d_in[2];
    const float* Wq     = (const float*)d_in[3];
    const float* bq     = (const float*)d_in[4];
    const float* Wk     = (const float*)d_in[5];
    const float* bk     = (const float*)d_in[6];
    const float* Wv     = (const float*)d_in[7];
    const float* bv     = (const float*)d_in[8];
    const float* Wo     = (const float*)d_in[9];
    const float* ln_g   = (const float*)d_in[10];
    const float* ln_b   = (const float*)d_in[11];

    __nv_bfloat16 *qp, *kp, *vp, *ap;
    float *tp;
    cudaGetSymbolAddress((void**)&qp, g_q);
    cudaGetSymbolAddress((void**)&kp, g_k);
    cudaGetSymbolAddress((void**)&vp, g_v);
    cudaGetSymbolAddress((void**)&ap, g_attn);
    cudaGetSymbolAddress((void**)&tp, g_tmp);

    dim3 gemmGrid(DMD/64, MROWS/128);   // (12, 64)

    gemm_bf16<float, true><<<gemmGrid, 256>>>(hidden, Wq, bq, nullptr, qp);
    gemm_bf16<float, true><<<gemmGrid, 256>>>(hidden, Wk, bk, nullptr, kp);
    gemm_bf16<float, true><<<gemmGrid, 256>>>(hidden, Wv, bv, nullptr, vp);

    rope_kernel<<<(BB*SS*NH*32)/256, 256>>>(qp, kp, cosb, sinb);

    attn_mma<<<dim3(SS/128, BB*NH), 256>>>(qp, kp, vp, ap);

    // out-proj + residual into tmp (fp32 for LN)
    gemm_bf16<__nv_bfloat16, false><<<gemmGrid, 256>>>(ap, Wo, nullptr, hidden, tp);

    ln_kernel<<<MROWS, 256>>>(tp, ln_g, ln_b, (float*)d_out);
}

// round 6
// speedup vs baseline: 7.4582x; 1.6254x over previous
#include <cuda_runtime.h>
#include <cuda_bf16.h>
#include <math.h>
#include <stdint.h>

#define BB 2
#define SS 4096
#define DMD 768
#define NH 12
#define HDD 64
#define MROWS (BB*SS)

// Scratch (static device globals — allocation-free rule)
__device__ __align__(16) __nv_bfloat16 g_q[MROWS*DMD];
__device__ __align__(16) __nv_bfloat16 g_k[MROWS*DMD];
__device__ __align__(16) __nv_bfloat16 g_v[MROWS*DMD];
__device__ __align__(16) __nv_bfloat16 g_attn[MROWS*DMD];
__device__ __align__(16) __nv_bfloat16 g_x[MROWS*DMD];
__device__ __align__(16) __nv_bfloat16 g_wq[DMD*DMD];
__device__ __align__(16) __nv_bfloat16 g_wk[DMD*DMD];
__device__ __align__(16) __nv_bfloat16 g_wv[DMD*DMD];
__device__ __align__(16) __nv_bfloat16 g_wo[DMD*DMD];
__device__ __align__(16) float         g_tmp[MROWS*DMD];

// ---------------------------------------------------------------------------
// Helpers
// ---------------------------------------------------------------------------
__device__ __forceinline__ uint32_t packbf(float a, float b) {
    __nv_bfloat162 h = __floats2bfloat162_rn(a, b);
    return *(uint32_t*)&h;
}
__device__ __forceinline__ void mma_bf16(float* c, const uint32_t* a,
                                         uint32_t b0, uint32_t b1) {
    asm volatile(
        "mma.sync.aligned.m16n8k16.row.col.f32.bf16.bf16.f32 "
        "{%0,%1,%2,%3}, {%4,%5,%6,%7}, {%8,%9}, {%0,%1,%2,%3};"
        : "+f"(c[0]), "+f"(c[1]), "+f"(c[2]), "+f"(c[3])
        : "r"(a[0]), "r"(a[1]), "r"(a[2]), "r"(a[3]), "r"(b0), "r"(b1));
}
__device__ __forceinline__ void cp16(uint32_t s, const void* g) {
    asm volatile("cp.async.cg.shared.global [%0], [%1], 16;" :: "r"(s), "l"(g));
}
__device__ __forceinline__ void cp_commit() {
    asm volatile("cp.async.commit_group;");
}
template<int N> __device__ __forceinline__ void cp_wait() {
    asm volatile("cp.async.wait_group %0;" :: "n"(N));
}
__device__ __forceinline__ void ldsm4t(uint32_t& r0, uint32_t& r1,
                                       uint32_t& r2, uint32_t& r3, uint32_t a) {
    asm volatile("ldmatrix.sync.aligned.m8n8.x4.trans.shared.b16 "
                 "{%0,%1,%2,%3}, [%4];"
                 : "=r"(r0), "=r"(r1), "=r"(r2), "=r"(r3) : "r"(a));
}
__device__ __forceinline__ uint32_t smaddr(const void* p) {
    return (uint32_t)__cvta_generic_to_shared(p);
}

// ---------------------------------------------------------------------------
// fp32 -> bf16 conversion (vectorized)
// ---------------------------------------------------------------------------
__global__ __launch_bounds__(256) void f2bf(
    const float* __restrict__ in, __nv_bfloat16* __restrict__ out, int n)
{
    int i = (blockIdx.x * blockDim.x + threadIdx.x) * 4;
    if (i >= n) return;
    float4 v = *(const float4*)(in + i);
    uint2 o;
    o.x = packbf(v.x, v.y);
    o.y = packbf(v.z, v.w);
    *(uint2*)(out + i) = o;
}

// ---------------------------------------------------------------------------
// bf16 GEMM core: out[M,N] = X[M,K] @ W[N,K]^T (+bias) (+residual)
// Tile 128x64, BK=32, 8 warps (4m x 2n), cp.async double-buffered.
// Smem rows: 32 halves = 16 words, stride GSW=20 words (conflict-free 20g+t).
// ---------------------------------------------------------------------------
#define GSW 20

template<bool OUT_BF16, bool HAS_RES>
__device__ __forceinline__ void gemm_body(
    const __nv_bfloat16* __restrict__ X, const __nv_bfloat16* __restrict__ W,
    const float* __restrict__ bias, const float* __restrict__ residual,
    void* __restrict__ outv,
    uint32_t (*As)[128*GSW], uint32_t (*Bs)[64*GSW])
{
    const int tid  = threadIdx.x;
    const int warp = tid >> 5;
    const int lane = tid & 31;
    const int g    = lane >> 2;
    const int t    = lane & 3;
    const int wm   = warp & 3;
    const int wn   = warp >> 2;
    const int row0 = blockIdx.y * 128;
    const int col0 = blockIdx.x * 64;

    uint32_t asa[2] = { smaddr(As[0]), smaddr(As[1]) };
    uint32_t bsa[2] = { smaddr(Bs[0]), smaddr(Bs[1]) };

    const int ar = tid >> 2;          // 0..63 (A uses +64 on second iter)
    const int ac8 = (tid & 3) * 8;    // 0,8,16,24 halves

    // prologue: stage 0
    {
        const int k0 = 0;
        cp16(asa[0] + (ar * GSW + ac8/2) * 4,
             X + (size_t)(row0 + ar) * DMD + k0 + ac8);
        cp16(asa[0] + ((ar + 64) * GSW + ac8/2) * 4,
             X + (size_t)(row0 + ar + 64) * DMD + k0 + ac8);
        cp16(bsa[0] + (ar * GSW + ac8/2) * 4,
             W + (size_t)(col0 + ar) * DMD + k0 + ac8);
        cp_commit();
    }

    float c[2][4][4] = {};
    int buf = 0;

    const int NKI = DMD / 32;   // 24
    for (int ki = 0; ki < NKI; ki++) {
        if (ki + 1 < NKI) {
            const int k0 = (ki + 1) * 32;
            const int nb = buf ^ 1;
            cp16(asa[nb] + (ar * GSW + ac8/2) * 4,
                 X + (size_t)(row0 + ar) * DMD + k0 + ac8);
            cp16(asa[nb] + ((ar + 64) * GSW + ac8/2) * 4,
                 X + (size_t)(row0 + ar + 64) * DMD + k0 + ac8);
            cp16(bsa[nb] + (ar * GSW + ac8/2) * 4,
                 W + (size_t)(col0 + ar) * DMD + k0 + ac8);
            cp_commit();
            cp_wait<1>();
        } else {
            cp_wait<0>();
        }
        __syncthreads();

        const uint32_t* Ap = As[buf];
        const uint32_t* Bp = Bs[buf];
        #pragma unroll
        for (int kt = 0; kt < 2; kt++) {
            uint32_t a[2][4];
            #pragma unroll
            for (int mt = 0; mt < 2; mt++) {
                int rm = wm * 32 + mt * 16;
                a[mt][0] = Ap[(rm + g    ) * GSW + kt * 8 + t    ];
                a[mt][1] = Ap[(rm + g + 8) * GSW + kt * 8 + t    ];
                a[mt][2] = Ap[(rm + g    ) * GSW + kt * 8 + t + 4];
                a[mt][3] = Ap[(rm + g + 8) * GSW + kt * 8 + t + 4];
            }
            #pragma unroll
            for (int nt = 0; nt < 4; nt++) {
                int nb = wn * 32 + nt * 8;
                uint32_t b0 = Bp[(nb + g) * GSW + kt * 8 + t    ];
                uint32_t b1 = Bp[(nb + g) * GSW + kt * 8 + t + 4];
                mma_bf16(c[0][nt], a[0], b0, b1);
                mma_bf16(c[1][nt], a[1], b0, b1);
            }
        }
        __syncthreads();
        buf ^= 1;
    }

    // Epilogue
    #pragma unroll
    for (int mt = 0; mt < 2; mt++) {
        #pragma unroll
        for (int nt = 0; nt < 4; nt++) {
            int r0 = row0 + wm * 32 + mt * 16 + g;
            int cc = col0 + wn * 32 + nt * 8 + 2 * t;
            float v0 = c[mt][nt][0], v1 = c[mt][nt][1];
            float v2 = c[mt][nt][2], v3 = c[mt][nt][3];
            if (bias) {
                float b0 = bias[cc], b1 = bias[cc + 1];
                v0 += b0; v1 += b1; v2 += b0; v3 += b1;
            }
            if constexpr (HAS_RES) {
                v0 += residual[(size_t)r0 * DMD + cc];
                v1 += residual[(size_t)r0 * DMD + cc + 1];
                v2 += residual[(size_t)(r0 + 8) * DMD + cc];
                v3 += residual[(size_t)(r0 + 8) * DMD + cc + 1];
            }
            if constexpr (OUT_BF16) {
                __nv_bfloat16* out = (__nv_bfloat16*)outv;
                *(uint32_t*)&out[(size_t)r0 * DMD + cc]       = packbf(v0, v1);
                *(uint32_t*)&out[(size_t)(r0 + 8) * DMD + cc] = packbf(v2, v3);
            } else {
                float* out = (float*)outv;
                *(float2*)&out[(size_t)r0 * DMD + cc]       = make_float2(v0, v1);
                *(float2*)&out[(size_t)(r0 + 8) * DMD + cc] = make_float2(v2, v3);
            }
        }
    }
}

// Fused QKV projection: grid.z in {0,1,2} selects which output
__global__ __launch_bounds__(256) void qkv_gemm(
    const __nv_bfloat16* __restrict__ X,
    const __nv_bfloat16* __restrict__ Wq, const __nv_bfloat16* __restrict__ Wk,
    const __nv_bfloat16* __restrict__ Wv,
    const float* __restrict__ bq, const float* __restrict__ bk,
    const float* __restrict__ bv,
    __nv_bfloat16* __restrict__ q, __nv_bfloat16* __restrict__ k,
    __nv_bfloat16* __restrict__ v)
{
    __shared__ uint32_t As[2][128*GSW];
    __shared__ uint32_t Bs[2][64*GSW];
    int z = blockIdx.z;
    const __nv_bfloat16* W = (z == 0) ? Wq : (z == 1) ? Wk : Wv;
    const float* bias      = (z == 0) ? bq : (z == 1) ? bk : bv;
    __nv_bfloat16* out     = (z == 0) ? q  : (z == 1) ? k  : v;
    gemm_body<true, false>(X, W, bias, nullptr, out, As, Bs);
}

// Output projection + residual (fp32 out)
__global__ __launch_bounds__(256) void oproj_gemm(
    const __nv_bfloat16* __restrict__ X, const __nv_bfloat16* __restrict__ W,
    const float* __restrict__ residual, float* __restrict__ out)
{
    __shared__ uint32_t As[2][128*GSW];
    __shared__ uint32_t Bs[2][64*GSW];
    gemm_body<false, true>(X, W, nullptr, residual, out, As, Bs);
}

// ---------------------------------------------------------------------------
// RoPE (in-place, bf16). q additionally scaled by 1/HD (both SCALINGs).
// ---------------------------------------------------------------------------
__global__ __launch_bounds__(256) void rope_kernel(
    __nv_bfloat16* __restrict__ q, __nv_bfloat16* __restrict__ k,
    const float* __restrict__ cosb, const float* __restrict__ sinb)
{
    int idx = blockIdx.x * blockDim.x + threadIdx.x;
    int d = idx & 31;
    int h = (idx >> 5) % NH;
    int s = (idx >> 5) / NH % SS;
    int b = idx / (32 * NH * SS);
    size_t base = ((size_t)(b * SS + s)) * DMD + h * HDD;
    float c1 = cosb[s*HDD + d],      s1 = sinb[s*HDD + d];
    float c2 = cosb[s*HDD + d + 32], s2 = sinb[s*HDD + d + 32];

    const float qs = 1.0f / (float)HDD;
    float q1 = __bfloat162float(q[base + d]);
    float q2 = __bfloat162float(q[base + d + 32]);
    q[base + d]      = __float2bfloat16((q1*c1 - q2*s1) * qs);
    q[base + d + 32] = __float2bfloat16((q2*c2 + q1*s2) * qs);

    float k1 = __bfloat162float(k[base + d]);
    float k2 = __bfloat162float(k[base + d + 32]);
    k[base + d]      = __float2bfloat16(k1*c1 - k2*s1);
    k[base + d + 32] = __float2bfloat16(k2*c2 + k1*s2);
}

// ---------------------------------------------------------------------------
// Flash attention, bf16 MMA, cp.async double-buffered K/V.
// Block: 128 q-rows, 8 warps (16 rows each). KV tiles of 64 keys.
// Smem rows = 64 halves = 32 words, stride KSW=36 (bank 4g+t, conflict-free;
// ldmatrix.trans rows also conflict-free). No max subtraction (scores |s|<1),
// P stays in registers (C-frag -> A-frag identity repack).
// ---------------------------------------------------------------------------
#define KSW 36
#define ATTN_SMEM ((128*KSW + 4*64*KSW) * 4)   // 55296 B

__global__ __launch_bounds__(256) void attn_mma(
    const __nv_bfloat16* __restrict__ Q, const __nv_bfloat16* __restrict__ K,
    const __nv_bfloat16* __restrict__ V, __nv_bfloat16* __restrict__ O)
{
    extern __shared__ uint32_t dsm[];
    uint32_t* Qs = dsm;                                  // 128 x KSW
    uint32_t* KsA[2] = { dsm + 128*KSW, dsm + 128*KSW + 64*KSW };
    uint32_t* VsA[2] = { dsm + 128*KSW + 2*64*KSW, dsm + 128*KSW + 3*64*KSW };

    const int tid  = threadIdx.x;
    const int warp = tid >> 5;
    const int lane = tid & 31;
    const int g    = lane >> 2;
    const int t    = lane & 3;
    const int rm   = warp * 16;
    const int bh   = blockIdx.y;
    const int b    = bh / NH, h = bh % NH;
    const int s0   = blockIdx.x * 128;

    const __nv_bfloat16* Qb = Q + (size_t)b * SS * DMD + h * HDD;
    const __nv_bfloat16* Kb = K + (size_t)b * SS * DMD + h * HDD;
    const __nv_bfloat16* Vb = V + (size_t)b * SS * DMD + h * HDD;

    uint32_t qsa    = smaddr(Qs);
    uint32_t ksa[2] = { smaddr(KsA[0]), smaddr(KsA[1]) };
    uint32_t vsa[2] = { smaddr(VsA[0]), smaddr(VsA[1]) };

    const int kvr  = tid >> 3;          // 0..31 (+32 on second iter)
    const int kvc8 = (tid & 7) * 8;     // 0..56 halves

    // Stage Q (128x64) + KV tile 0, one group
    #pragma unroll
    for (int it = 0; it < 4; it++) {
        int i = tid + it * 256;
        int r = i >> 3, c8 = (i & 7) * 8;
        cp16(qsa + (r * KSW + c8/2) * 4, Qb + (size_t)(s0 + r) * DMD + c8);
    }
    cp16(ksa[0] + (kvr * KSW + kvc8/2) * 4, Kb + (size_t)kvr * DMD + kvc8);
    cp16(ksa[0] + ((kvr+32) * KSW + kvc8/2) * 4, Kb + (size_t)(kvr+32) * DMD + kvc8);
    cp16(vsa[0] + (kvr * KSW + kvc8/2) * 4, Vb + (size_t)kvr * DMD + kvc8);
    cp16(vsa[0] + ((kvr+32) * KSW + kvc8/2) * 4, Vb + (size_t)(kvr+32) * DMD + kvc8);
    cp_commit();
    cp_wait<0>();
    __syncthreads();

    // Persistent Q fragments
    uint32_t qa[4][4];
    #pragma unroll
    for (int kt = 0; kt < 4; kt++) {
        qa[kt][0] = Qs[(rm + g    ) * KSW + kt * 8 + t    ];
        qa[kt][1] = Qs[(rm + g + 8) * KSW + kt * 8 + t    ];
        qa[kt][2] = Qs[(rm + g    ) * KSW + kt * 8 + t + 4];
        qa[kt][3] = Qs[(rm + g + 8) * KSW + kt * 8 + t + 4];
    }

    // ldmatrix lane addressing for V (trans)
    const int vrow  = (lane & 7) + ((lane >> 3) & 1) * 8;
    const int vcolw = (lane >> 4) * 4;   // words

    float o[8][4] = {};
    float l0 = 0.0f, l1 = 0.0f;
    int buf = 0;

    for (int t0 = 0; t0 < SS; t0 += 64) {
        if (t0 + 64 < SS) {
            const int nb = buf ^ 1;
            const __nv_bfloat16* Kg = Kb + (size_t)(t0 + 64) * DMD;
            const __nv_bfloat16* Vg = Vb + (size_t)(t0 + 64) * DMD;
            cp16(ksa[nb] + (kvr * KSW + kvc8/2) * 4, Kg + (size_t)kvr * DMD + kvc8);
            cp16(ksa[nb] + ((kvr+32) * KSW + kvc8/2) * 4, Kg + (size_t)(kvr+32) * DMD + kvc8);
            cp16(vsa[nb] + (kvr * KSW + kvc8/2) * 4, Vg + (size_t)kvr * DMD + kvc8);
            cp16(vsa[nb] + ((kvr+32) * KSW + kvc8/2) * 4, Vg + (size_t)(kvr+32) * DMD + kvc8);
            cp_commit();
            cp_wait<1>();
        } else {
            cp_wait<0>();
        }
        __syncthreads();

        // S = Q K^T  (q already carries 1/HD)
        const uint32_t* Kp = KsA[buf];
        float s[8][4] = {};
        #pragma unroll
        for (int nt = 0; nt < 8; nt++) {
            #pragma unroll
            for (int kt = 0; kt < 4; kt++) {
                uint32_t b0 = Kp[(nt * 8 + g) * KSW + kt * 8 + t    ];
                uint32_t b1 = Kp[(nt * 8 + g) * KSW + kt * 8 + t + 4];
                mma_bf16(s[nt], qa[kt], b0, b1);
            }
        }

        // exp (no max needed: |s| < 1) + accumulate row sums
        #pragma unroll
        for (int nt = 0; nt < 8; nt++) {
            s[nt][0] = __expf(s[nt][0]);
            s[nt][1] = __expf(s[nt][1]);
            s[nt][2] = __expf(s[nt][2]);
            s[nt][3] = __expf(s[nt][3]);
            l0 += s[nt][0] + s[nt][1];
            l1 += s[nt][2] + s[nt][3];
        }

        // O += P V  (P repacked in registers; V B-frags via ldmatrix.trans)
        uint32_t vb = vsa[buf];
        #pragma unroll
        for (int kt = 0; kt < 4; kt++) {
            uint32_t pa[4];
            pa[0] = packbf(s[2*kt  ][0], s[2*kt  ][1]);
            pa[1] = packbf(s[2*kt  ][2], s[2*kt  ][3]);
            pa[2] = packbf(s[2*kt+1][0], s[2*kt+1][1]);
            pa[3] = packbf(s[2*kt+1][2], s[2*kt+1][3]);
            #pragma unroll
            for (int np = 0; np < 4; np++) {
                uint32_t b0, b1, b2, b3;
                uint32_t addr = vb + (((kt*16 + vrow) * KSW) + np*8 + vcolw) * 4;
                ldsm4t(b0, b1, b2, b3, addr);
                mma_bf16(o[2*np  ], pa, b0, b1);
                mma_bf16(o[2*np+1], pa, b2, b3);
            }
        }
        __syncthreads();
        buf ^= 1;
    }

    // Final cross-lane (quad) sum reduction, normalize, store
    l0 += __shfl_xor_sync(0xffffffffu, l0, 1);
    l0 += __shfl_xor_sync(0xffffffffu, l0, 2);
    l1 += __shfl_xor_sync(0xffffffffu, l1, 1);
    l1 += __shfl_xor_sync(0xffffffffu, l1, 2);
    float inv0 = 1.0f / l0, inv1 = 1.0f / l1;

    __nv_bfloat16* Ob = O + (size_t)b * SS * DMD + h * HDD;
    #pragma unroll
    for (int nt = 0; nt < 8; nt++) {
        int cc = nt * 8 + 2 * t;
        *(uint32_t*)&Ob[(size_t)(s0 + rm + g) * DMD + cc] =
            packbf(o[nt][0] * inv0, o[nt][1] * inv0);
        *(uint32_t*)&Ob[(size_t)(s0 + rm + g + 8) * DMD + cc] =
            packbf(o[nt][2] * inv1, o[nt][3] * inv1);
    }
}

// ---------------------------------------------------------------------------
// LayerNorm over rows of 768. One block per row.
// ---------------------------------------------------------------------------
__global__ __launch_bounds__(256) void ln_kernel(
    const float* __restrict__ X, const float* __restrict__ gamma,
    const float* __restrict__ beta, float* __restrict__ out)
{
    const int row = blockIdx.x;
    const float* xr = X + (size_t)row * DMD;
    const int t = threadIdx.x;
    float x0 = xr[t], x1 = xr[t + 256], x2 = xr[t + 512];
    float sum = x0 + x1 + x2;
    float sq  = x0*x0 + x1*x1 + x2*x2;
    #pragma unroll
    for (int off = 16; off > 0; off >>= 1) {
        sum += __shfl_xor_sync(0xffffffffu, sum, off);
        sq  += __shfl_xor_sync(0xffffffffu, sq,  off);
    }
    __shared__ float wsum[8], wsq[8];
    __shared__ float s_mean, s_rstd;
    int wid = t >> 5, lane = t & 31;
    if (lane == 0) { wsum[wid] = sum; wsq[wid] = sq; }
    __syncthreads();
    if (t == 0) {
        float ts = 0.f, tq = 0.f;
        #pragma unroll
        for (int i = 0; i < 8; i++) { ts += wsum[i]; tq += wsq[i]; }
        float mean = ts * (1.0f / DMD);
        float var  = tq * (1.0f / DMD) - mean * mean;
        s_mean = mean;
        s_rstd = rsqrtf(var + 1e-12f);
    }
    __syncthreads();
    float mean = s_mean, rstd = s_rstd;
    out[(size_t)row*DMD + t      ] = (x0 - mean)*rstd*gamma[t      ] + beta[t      ];
    out[(size_t)row*DMD + t + 256] = (x1 - mean)*rstd*gamma[t + 256] + beta[t + 256];
    out[(size_t)row*DMD + t + 512] = (x2 - mean)*rstd*gamma[t + 512] + beta[t + 512];
}

// ---------------------------------------------------------------------------
extern "C" void kernel_launch(void* const* d_in, const int* in_sizes, int n_in,
                              void* d_out, int out_size)
{
    const float* hidden = (const float*)d_in[0];
    const float* cosb   = (const float*)d_in[1];
    const float* sinb   = (const float*)d_in[2];
    const float* Wq     = (const float*)d_in[3];
    const float* bq     = (const float*)d_in[4];
    const float* Wk     = (const float*)d_in[5];
    const float* bk     = (const float*)d_in[6];
    const float* Wv     = (const float*)d_in[7];
    const float* bv     = (const float*)d_in[8];
    const float* Wo     = (const float*)d_in[9];
    const float* ln_g   = (const float*)d_in[10];
    const float* ln_b   = (const float*)d_in[11];

    __nv_bfloat16 *qp, *kp, *vp, *ap, *xp, *wqp, *wkp, *wvp, *wop;
    float *tp;
    cudaGetSymbolAddress((void**)&qp,  g_q);
    cudaGetSymbolAddress((void**)&kp,  g_k);
    cudaGetSymbolAddress((void**)&vp,  g_v);
    cudaGetSymbolAddress((void**)&ap,  g_attn);
    cudaGetSymbolAddress((void**)&xp,  g_x);
    cudaGetSymbolAddress((void**)&wqp, g_wq);
    cudaGetSymbolAddress((void**)&wkp, g_wk);
    cudaGetSymbolAddress((void**)&wvp, g_wv);
    cudaGetSymbolAddress((void**)&wop, g_wo);
    cudaGetSymbolAddress((void**)&tp,  g_tmp);

    // Convert inputs to bf16
    f2bf<<<(MROWS*DMD/4 + 255)/256, 256>>>(hidden, xp, MROWS*DMD);
    f2bf<<<(DMD*DMD/4 + 255)/256, 256>>>(Wq, wqp, DMD*DMD);
    f2bf<<<(DMD*DMD/4 + 255)/256, 256>>>(Wk, wkp, DMD*DMD);
    f2bf<<<(DMD*DMD/4 + 255)/256, 256>>>(Wv, wvp, DMD*DMD);
    f2bf<<<(DMD*DMD/4 + 255)/256, 256>>>(Wo, wop, DMD*DMD);

    // Fused QKV projections
    qkv_gemm<<<dim3(DMD/64, MROWS/128, 3), 256>>>(
        xp, wqp, wkp, wvp, bq, bk, bv, qp, kp, vp);

    rope_kernel<<<(BB*SS*NH*32)/256, 256>>>(qp, kp, cosb, sinb);

    cudaFuncSetAttribute(attn_mma,
                         cudaFuncAttributeMaxDynamicSharedMemorySize, ATTN_SMEM);
    attn_mma<<<dim3(SS/128, BB*NH), 256, ATTN_SMEM>>>(qp, kp, vp, ap);

    // out-proj + residual into tmp (fp32 for LN)
    oproj_gemm<<<dim3(DMD/64, MROWS/128), 256>>>(ap, wop, hidden, tp);

    ln_kernel<<<MROWS, 256>>>(tp, ln_g, ln_b, (float*)d_out);
}

// round 8
// speedup vs baseline: 8.5777x; 1.1501x over previous
#include <cuda_runtime.h>
#include <cuda_bf16.h>
#include <math.h>
#include <stdint.h>

#define BB 2
#define SS 4096
#define DMD 768
#define NH 12
#define HDD 64
#define MROWS (BB*SS)

// Scratch (static device globals — allocation-free rule)
__device__ __align__(16) __nv_bfloat16 g_q[MROWS*DMD];
__device__ __align__(16) __nv_bfloat16 g_k[MROWS*DMD];
__device__ __align__(16) __nv_bfloat16 g_v[MROWS*DMD];
__device__ __align__(16) __nv_bfloat16 g_attn[MROWS*DMD];
__device__ __align__(16) __nv_bfloat16 g_x[MROWS*DMD];
__device__ __align__(16) __nv_bfloat16 g_wq[DMD*DMD];
__device__ __align__(16) __nv_bfloat16 g_wk[DMD*DMD];
__device__ __align__(16) __nv_bfloat16 g_wv[DMD*DMD];
__device__ __align__(16) __nv_bfloat16 g_wo[DMD*DMD];
__device__ __align__(16) float         g_tmp[MROWS*DMD];

// ---------------------------------------------------------------------------
// Helpers
// ---------------------------------------------------------------------------
__device__ __forceinline__ uint32_t packbf(float a, float b) {
    __nv_bfloat162 h = __floats2bfloat162_rn(a, b);
    return *(uint32_t*)&h;
}
__device__ __forceinline__ void mma_bf16(float* c, const uint32_t* a,
                                         uint32_t b0, uint32_t b1) {
    asm volatile(
        "mma.sync.aligned.m16n8k16.row.col.f32.bf16.bf16.f32 "
        "{%0,%1,%2,%3}, {%4,%5,%6,%7}, {%8,%9}, {%0,%1,%2,%3};"
        : "+f"(c[0]), "+f"(c[1]), "+f"(c[2]), "+f"(c[3])
        : "r"(a[0]), "r"(a[1]), "r"(a[2]), "r"(a[3]), "r"(b0), "r"(b1));
}
__device__ __forceinline__ void cp16(uint32_t s, const void* g) {
    asm volatile("cp.async.cg.shared.global [%0], [%1], 16;" :: "r"(s), "l"(g));
}
__device__ __forceinline__ void cp_commit() {
    asm volatile("cp.async.commit_group;");
}
template<int N> __device__ __forceinline__ void cp_wait() {
    asm volatile("cp.async.wait_group %0;" :: "n"(N));
}
__device__ __forceinline__ void ldsm4(uint32_t& r0, uint32_t& r1,
                                      uint32_t& r2, uint32_t& r3, uint32_t a) {
    asm volatile("ldmatrix.sync.aligned.m8n8.x4.shared.b16 "
                 "{%0,%1,%2,%3}, [%4];"
                 : "=r"(r0), "=r"(r1), "=r"(r2), "=r"(r3) : "r"(a));
}
__device__ __forceinline__ void ldsm4t(uint32_t& r0, uint32_t& r1,
                                       uint32_t& r2, uint32_t& r3, uint32_t a) {
    asm volatile("ldmatrix.sync.aligned.m8n8.x4.trans.shared.b16 "
                 "{%0,%1,%2,%3}, [%4];"
                 : "=r"(r0), "=r"(r1), "=r"(r2), "=r"(r3) : "r"(a));
}
__device__ __forceinline__ uint32_t smaddr(const void* p) {
    return (uint32_t)__cvta_generic_to_shared(p);
}

// ---------------------------------------------------------------------------
// fp32 -> bf16 conversion (vectorized); single-tensor and fused 4-weight forms
// ---------------------------------------------------------------------------
__global__ __launch_bounds__(256) void f2bf(
    const float* __restrict__ in, __nv_bfloat16* __restrict__ out, int n)
{
    int i = (blockIdx.x * blockDim.x + threadIdx.x) * 4;
    if (i >= n) return;
    float4 v = *(const float4*)(in + i);
    uint2 o;
    o.x = packbf(v.x, v.y);
    o.y = packbf(v.z, v.w);
    *(uint2*)(out + i) = o;
}

__global__ __launch_bounds__(256) void f2bf_w4(
    const float* __restrict__ w0, const float* __restrict__ w1,
    const float* __restrict__ w2, const float* __restrict__ w3,
    __nv_bfloat16* __restrict__ o0, __nv_bfloat16* __restrict__ o1,
    __nv_bfloat16* __restrict__ o2, __nv_bfloat16* __restrict__ o3)
{
    int z = blockIdx.y;
    const float* in = (z == 0) ? w0 : (z == 1) ? w1 : (z == 2) ? w2 : w3;
    __nv_bfloat16* out = (z == 0) ? o0 : (z == 1) ? o1 : (z == 2) ? o2 : o3;
    int i = (blockIdx.x * blockDim.x + threadIdx.x) * 4;
    if (i >= DMD * DMD) return;
    float4 v = *(const float4*)(in + i);
    uint2 o;
    o.x = packbf(v.x, v.y);
    o.y = packbf(v.z, v.w);
    *(uint2*)(out + i) = o;
}

// ---------------------------------------------------------------------------
// bf16 GEMM core: out[M,N] = X[M,K] @ W[N,K]^T (+bias) (+residual)
// Tile 128x64, BK=32, 8 warps (4m x 2n), cp.async double-buffered.
// ---------------------------------------------------------------------------
#define GSW 20

template<bool OUT_BF16, bool HAS_RES>
__device__ __forceinline__ void gemm_body(
    const __nv_bfloat16* __restrict__ X, const __nv_bfloat16* __restrict__ W,
    const float* __restrict__ bias, const float* __restrict__ residual,
    void* __restrict__ outv,
    uint32_t (*As)[128*GSW], uint32_t (*Bs)[64*GSW])
{
    const int tid  = threadIdx.x;
    const int warp = tid >> 5;
    const int lane = tid & 31;
    const int g    = lane >> 2;
    const int t    = lane & 3;
    const int wm   = warp & 3;
    const int wn   = warp >> 2;
    const int row0 = blockIdx.y * 128;
    const int col0 = blockIdx.x * 64;

    uint32_t asa[2] = { smaddr(As[0]), smaddr(As[1]) };
    uint32_t bsa[2] = { smaddr(Bs[0]), smaddr(Bs[1]) };

    const int ar = tid >> 2;
    const int ac8 = (tid & 3) * 8;

    {
        cp16(asa[0] + (ar * GSW + ac8/2) * 4, X + (size_t)(row0 + ar) * DMD + ac8);
        cp16(asa[0] + ((ar + 64) * GSW + ac8/2) * 4,
             X + (size_t)(row0 + ar + 64) * DMD + ac8);
        cp16(bsa[0] + (ar * GSW + ac8/2) * 4, W + (size_t)(col0 + ar) * DMD + ac8);
        cp_commit();
    }

    float c[2][4][4] = {};
    int buf = 0;

    const int NKI = DMD / 32;
    for (int ki = 0; ki < NKI; ki++) {
        if (ki + 1 < NKI) {
            const int k0 = (ki + 1) * 32;
            const int nb = buf ^ 1;
            cp16(asa[nb] + (ar * GSW + ac8/2) * 4,
                 X + (size_t)(row0 + ar) * DMD + k0 + ac8);
            cp16(asa[nb] + ((ar + 64) * GSW + ac8/2) * 4,
                 X + (size_t)(row0 + ar + 64) * DMD + k0 + ac8);
            cp16(bsa[nb] + (ar * GSW + ac8/2) * 4,
                 W + (size_t)(col0 + ar) * DMD + k0 + ac8);
            cp_commit();
            cp_wait<1>();
        } else {
            cp_wait<0>();
        }
        __syncthreads();

        const uint32_t* Ap = As[buf];
        const uint32_t* Bp = Bs[buf];
        #pragma unroll
        for (int kt = 0; kt < 2; kt++) {
            uint32_t a[2][4];
            #pragma unroll
            for (int mt = 0; mt < 2; mt++) {
                int rm = wm * 32 + mt * 16;
                a[mt][0] = Ap[(rm + g    ) * GSW + kt * 8 + t    ];
                a[mt][1] = Ap[(rm + g + 8) * GSW + kt * 8 + t    ];
                a[mt][2] = Ap[(rm + g    ) * GSW + kt * 8 + t + 4];
                a[mt][3] = Ap[(rm + g + 8) * GSW + kt * 8 + t + 4];
            }
            #pragma unroll
            for (int nt = 0; nt < 4; nt++) {
                int nb = wn * 32 + nt * 8;
                uint32_t b0 = Bp[(nb + g) * GSW + kt * 8 + t    ];
                uint32_t b1 = Bp[(nb + g) * GSW + kt * 8 + t + 4];
                mma_bf16(c[0][nt], a[0], b0, b1);
                mma_bf16(c[1][nt], a[1], b0, b1);
            }
        }
        __syncthreads();
        buf ^= 1;
    }

    #pragma unroll
    for (int mt = 0; mt < 2; mt++) {
        #pragma unroll
        for (int nt = 0; nt < 4; nt++) {
            int r0 = row0 + wm * 32 + mt * 16 + g;
            int cc = col0 + wn * 32 + nt * 8 + 2 * t;
            float v0 = c[mt][nt][0], v1 = c[mt][nt][1];
            float v2 = c[mt][nt][2], v3 = c[mt][nt][3];
            if (bias) {
                float b0 = bias[cc], b1 = bias[cc + 1];
                v0 += b0; v1 += b1; v2 += b0; v3 += b1;
            }
            if constexpr (HAS_RES) {
                v0 += residual[(size_t)r0 * DMD + cc];
                v1 += residual[(size_t)r0 * DMD + cc + 1];
                v2 += residual[(size_t)(r0 + 8) * DMD + cc];
                v3 += residual[(size_t)(r0 + 8) * DMD + cc + 1];
            }
            if constexpr (OUT_BF16) {
                __nv_bfloat16* out = (__nv_bfloat16*)outv;
                *(uint32_t*)&out[(size_t)r0 * DMD + cc]       = packbf(v0, v1);
                *(uint32_t*)&out[(size_t)(r0 + 8) * DMD + cc] = packbf(v2, v3);
            } else {
                float* out = (float*)outv;
                *(float2*)&out[(size_t)r0 * DMD + cc]       = make_float2(v0, v1);
                *(float2*)&out[(size_t)(r0 + 8) * DMD + cc] = make_float2(v2, v3);
            }
        }
    }
}

__global__ __launch_bounds__(256) void qkv_gemm(
    const __nv_bfloat16* __restrict__ X,
    const __nv_bfloat16* __restrict__ Wq, const __nv_bfloat16* __restrict__ Wk,
    const __nv_bfloat16* __restrict__ Wv,
    const float* __restrict__ bq, const float* __restrict__ bk,
    const float* __restrict__ bv,
    __nv_bfloat16* __restrict__ q, __nv_bfloat16* __restrict__ k,
    __nv_bfloat16* __restrict__ v)
{
    __shared__ uint32_t As[2][128*GSW];
    __shared__ uint32_t Bs[2][64*GSW];
    int z = blockIdx.z;
    const __nv_bfloat16* W = (z == 0) ? Wq : (z == 1) ? Wk : Wv;
    const float* bias      = (z == 0) ? bq : (z == 1) ? bk : bv;
    __nv_bfloat16* out     = (z == 0) ? q  : (z == 1) ? k  : v;
    gemm_body<true, false>(X, W, bias, nullptr, out, As, Bs);
}

__global__ __launch_bounds__(256) void oproj_gemm(
    const __nv_bfloat16* __restrict__ X, const __nv_bfloat16* __restrict__ W,
    const float* __restrict__ residual, float* __restrict__ out)
{
    __shared__ uint32_t As[2][128*GSW];
    __shared__ uint32_t Bs[2][64*GSW];
    gemm_body<false, true>(X, W, nullptr, residual, out, As, Bs);
}

// ---------------------------------------------------------------------------
// RoPE (in-place, bf16). q additionally scaled by 1/HD (both SCALINGs).
// ---------------------------------------------------------------------------
__global__ __launch_bounds__(256) void rope_kernel(
    __nv_bfloat16* __restrict__ q, __nv_bfloat16* __restrict__ k,
    const float* __restrict__ cosb, const float* __restrict__ sinb)
{
    int idx = blockIdx.x * blockDim.x + threadIdx.x;
    int d = idx & 31;
    int h = (idx >> 5) % NH;
    int s = (idx >> 5) / NH % SS;
    int b = idx / (32 * NH * SS);
    size_t base = ((size_t)(b * SS + s)) * DMD + h * HDD;
    float c1 = cosb[s*HDD + d],      s1 = sinb[s*HDD + d];
    float c2 = cosb[s*HDD + d + 32], s2 = sinb[s*HDD + d + 32];

    const float qs = 1.0f / (float)HDD;
    float q1 = __bfloat162float(q[base + d]);
    float q2 = __bfloat162float(q[base + d + 32]);
    q[base + d]      = __float2bfloat16((q1*c1 - q2*s1) * qs);
    q[base + d + 32] = __float2bfloat16((q2*c2 + q1*s2) * qs);

    float k1 = __bfloat162float(k[base + d]);
    float k2 = __bfloat162float(k[base + d + 32]);
    k[base + d]      = __float2bfloat16(k1*c1 - k2*s1);
    k[base + d + 32] = __float2bfloat16(k2*c2 + k1*s2);
}

// ---------------------------------------------------------------------------
// Flash attention, bf16 MMA. CTA = 128 threads (4 warps), 128 q-rows,
// each warp owns 32 rows (2 x m16). KV tiles of 64 keys, cp.async
// double-buffered. K frags via ldmatrix.x4, V frags via ldmatrix.x4.trans.
// Smem stride 36 words (conflict-free). No softmax max-subtraction
// (scores |s| < 1); P stays in registers.
// ---------------------------------------------------------------------------
#define KSW 36
#define ATTN_SMEM ((128*KSW + 4*64*KSW) * 4)   // 55296 B

__global__ __launch_bounds__(128, 2) void attn_mma(
    const __nv_bfloat16* __restrict__ Q, const __nv_bfloat16* __restrict__ K,
    const __nv_bfloat16* __restrict__ V, __nv_bfloat16* __restrict__ O)
{
    extern __shared__ uint32_t dsm[];
    uint32_t* Qs = dsm;                                  // 128 x KSW
    uint32_t ksa[2] = { smaddr(dsm + 128*KSW),
                        smaddr(dsm + 128*KSW + 64*KSW) };
    uint32_t vsa[2] = { smaddr(dsm + 128*KSW + 2*64*KSW),
                        smaddr(dsm + 128*KSW + 3*64*KSW) };

    const int tid  = threadIdx.x;
    const int warp = tid >> 5;
    const int lane = tid & 31;
    const int g    = lane >> 2;
    const int t    = lane & 3;
    const int rm   = warp * 32;
    const int bh   = blockIdx.y;
    const int b    = bh / NH, h = bh % NH;
    const int s0   = blockIdx.x * 128;

    const __nv_bfloat16* Qb = Q + (size_t)b * SS * DMD + h * HDD;
    const __nv_bfloat16* Kb = K + (size_t)b * SS * DMD + h * HDD;
    const __nv_bfloat16* Vb = V + (size_t)b * SS * DMD + h * HDD;

    uint32_t qsa = smaddr(Qs);

    // Stage Q (128x64 halves): 1024 cp16 / 128 threads
    #pragma unroll
    for (int it = 0; it < 8; it++) {
        int i = tid + it * 128;
        int r = i >> 3, c8 = (i & 7) * 8;
        cp16(qsa + (r * KSW + c8/2) * 4, Qb + (size_t)(s0 + r) * DMD + c8);
    }
    // KV tile 0
    #pragma unroll
    for (int it = 0; it < 4; it++) {
        int i = tid + it * 128;
        int r = i >> 3, c8 = (i & 7) * 8;
        cp16(ksa[0] + (r * KSW + c8/2) * 4, Kb + (size_t)r * DMD + c8);
        cp16(vsa[0] + (r * KSW + c8/2) * 4, Vb + (size_t)r * DMD + c8);
    }
    cp_commit();
    cp_wait<0>();
    __syncthreads();

    // Persistent Q fragments: 2 m-tiles x 4 k-blocks
    uint32_t qa[2][4][4];
    #pragma unroll
    for (int mt = 0; mt < 2; mt++) {
        int rb = rm + mt * 16;
        #pragma unroll
        for (int kt = 0; kt < 4; kt++) {
            qa[mt][kt][0] = Qs[(rb + g    ) * KSW + kt * 8 + t    ];
            qa[mt][kt][1] = Qs[(rb + g + 8) * KSW + kt * 8 + t    ];
            qa[mt][kt][2] = Qs[(rb + g    ) * KSW + kt * 8 + t + 4];
            qa[mt][kt][3] = Qs[(rb + g + 8) * KSW + kt * 8 + t + 4];
        }
    }

    // ldmatrix lane addressing
    const int krow_i = (lane & 7) + (lane >> 4) * 8;          // K: row within ntp pair
    const int kcol_i = ((lane >> 3) & 1) * 4;                 // K: word offset (b0/b1)
    const int vrow   = (lane & 7) + ((lane >> 3) & 1) * 8;    // V trans
    const int vcolw  = (lane >> 4) * 4;

    float o[2][8][4] = {};
    float l00 = 0.f, l01 = 0.f, l10 = 0.f, l11 = 0.f;
    int buf = 0;

    for (int t0 = 0; t0 < SS; t0 += 64) {
        if (t0 + 64 < SS) {
            const int nb = buf ^ 1;
            const __nv_bfloat16* Kg = Kb + (size_t)(t0 + 64) * DMD;
            const __nv_bfloat16* Vg = Vb + (size_t)(t0 + 64) * DMD;
            #pragma unroll
            for (int it = 0; it < 4; it++) {
                int i = tid + it * 128;
                int r = i >> 3, c8 = (i & 7) * 8;
                cp16(ksa[nb] + (r * KSW + c8/2) * 4, Kg + (size_t)r * DMD + c8);
                cp16(vsa[nb] + (r * KSW + c8/2) * 4, Vg + (size_t)r * DMD + c8);
            }
            cp_commit();
            cp_wait<1>();
        } else {
            cp_wait<0>();
        }
        __syncthreads();

        // S = Q K^T  (q already carries 1/HD)
        float s[2][8][4] = {};
        #pragma unroll
        for (int kt = 0; kt < 4; kt++) {
            #pragma unroll
            for (int ntp = 0; ntp < 4; ntp++) {
                uint32_t r0, r1, r2, r3;
                uint32_t addr = ksa[buf] +
                    (((ntp * 16 + krow_i) * KSW) + kt * 8 + kcol_i) * 4;
                ldsm4(r0, r1, r2, r3, addr);
                mma_bf16(s[0][2*ntp  ], qa[0][kt], r0, r1);
                mma_bf16(s[1][2*ntp  ], qa[1][kt], r0, r1);
                mma_bf16(s[0][2*ntp+1], qa[0][kt], r2, r3);
                mma_bf16(s[1][2*ntp+1], qa[1][kt], r2, r3);
            }
        }

        // exp (no max: |s| < 1) + row-sum accumulation
        #pragma unroll
        for (int nt = 0; nt < 8; nt++) {
            s[0][nt][0] = __expf(s[0][nt][0]);
            s[0][nt][1] = __expf(s[0][nt][1]);
            s[0][nt][2] = __expf(s[0][nt][2]);
            s[0][nt][3] = __expf(s[0][nt][3]);
            l00 += s[0][nt][0] + s[0][nt][1];
            l01 += s[0][nt][2] + s[0][nt][3];
            s[1][nt][0] = __expf(s[1][nt][0]);
            s[1][nt][1] = __expf(s[1][nt][1]);
            s[1][nt][2] = __expf(s[1][nt][2]);
            s[1][nt][3] = __expf(s[1][nt][3]);
            l10 += s[1][nt][0] + s[1][nt][1];
            l11 += s[1][nt][2] + s[1][nt][3];
        }

        // O += P V  (P register repack; V frags via ldmatrix.trans)
        #pragma unroll
        for (int kt = 0; kt < 4; kt++) {
            uint32_t pa0[4], pa1[4];
            pa0[0] = packbf(s[0][2*kt  ][0], s[0][2*kt  ][1]);
            pa0[1] = packbf(s[0][2*kt  ][2], s[0][2*kt  ][3]);
            pa0[2] = packbf(s[0][2*kt+1][0], s[0][2*kt+1][1]);
            pa0[3] = packbf(s[0][2*kt+1][2], s[0][2*kt+1][3]);
            pa1[0] = packbf(s[1][2*kt  ][0], s[1][2*kt  ][1]);
            pa1[1] = packbf(s[1][2*kt  ][2], s[1][2*kt  ][3]);
            pa1[2] = packbf(s[1][2*kt+1][0], s[1][2*kt+1][1]);
            pa1[3] = packbf(s[1][2*kt+1][2], s[1][2*kt+1][3]);
            #pragma unroll
            for (int np = 0; np < 4; np++) {
                uint32_t b0, b1, b2, b3;
                uint32_t addr = vsa[buf] +
                    (((kt*16 + vrow) * KSW) + np*8 + vcolw) * 4;
                ldsm4t(b0, b1, b2, b3, addr);
                mma_bf16(o[0][2*np  ], pa0, b0, b1);
                mma_bf16(o[0][2*np+1], pa0, b2, b3);
                mma_bf16(o[1][2*np  ], pa1, b0, b1);
                mma_bf16(o[1][2*np+1], pa1, b2, b3);
            }
        }
        __syncthreads();
        buf ^= 1;
    }

    // Quad reduction of row sums, normalize, store
    l00 += __shfl_xor_sync(0xffffffffu, l00, 1);
    l00 += __shfl_xor_sync(0xffffffffu, l00, 2);
    l01 += __shfl_xor_sync(0xffffffffu, l01, 1);
    l01 += __shfl_xor_sync(0xffffffffu, l01, 2);
    l10 += __shfl_xor_sync(0xffffffffu, l10, 1);
    l10 += __shfl_xor_sync(0xffffffffu, l10, 2);
    l11 += __shfl_xor_sync(0xffffffffu, l11, 1);
    l11 += __shfl_xor_sync(0xffffffffu, l11, 2);
    float inv[2][2] = { {1.0f / l00, 1.0f / l01}, {1.0f / l10, 1.0f / l11} };

    __nv_bfloat16* Ob = O + (size_t)b * SS * DMD + h * HDD;
    #pragma unroll
    for (int mt = 0; mt < 2; mt++) {
        int rb = s0 + rm + mt * 16;
        #pragma unroll
        for (int nt = 0; nt < 8; nt++) {
            int cc = nt * 8 + 2 * t;
            *(uint32_t*)&Ob[(size_t)(rb + g) * DMD + cc] =
                packbf(o[mt][nt][0] * inv[mt][0], o[mt][nt][1] * inv[mt][0]);
            *(uint32_t*)&Ob[(size_t)(rb + g + 8) * DMD + cc] =
                packbf(o[mt][nt][2] * inv[mt][1], o[mt][nt][3] * inv[mt][1]);
        }
    }
}

// ---------------------------------------------------------------------------
// LayerNorm over rows of 768. One block per row.
// ---------------------------------------------------------------------------
__global__ __launch_bounds__(256) void ln_kernel(
    const float* __restrict__ X, const float* __restrict__ gamma,
    const float* __restrict__ beta, float* __restrict__ out)
{
    const int row = blockIdx.x;
    const float* xr = X + (size_t)row * DMD;
    const int t = threadIdx.x;
    float x0 = xr[t], x1 = xr[t + 256], x2 = xr[t + 512];
    float sum = x0 + x1 + x2;
    float sq  = x0*x0 + x1*x1 + x2*x2;
    #pragma unroll
    for (int off = 16; off > 0; off >>= 1) {
        sum += __shfl_xor_sync(0xffffffffu, sum, off);
        sq  += __shfl_xor_sync(0xffffffffu, sq,  off);
    }
    __shared__ float wsum[8], wsq[8];
    __shared__ float s_mean, s_rstd;
    int wid = t >> 5, lane = t & 31;
    if (lane == 0) { wsum[wid] = sum; wsq[wid] = sq; }
    __syncthreads();
    if (t == 0) {
        float ts = 0.f, tq = 0.f;
        #pragma unroll
        for (int i = 0; i < 8; i++) { ts += wsum[i]; tq += wsq[i]; }
        float mean = ts * (1.0f / DMD);
        float var  = tq * (1.0f / DMD) - mean * mean;
        s_mean = mean;
        s_rstd = rsqrtf(var + 1e-12f);
    }
    __syncthreads();
    float mean = s_mean, rstd = s_rstd;
    out[(size_t)row*DMD + t      ] = (x0 - mean)*rstd*gamma[t      ] + beta[t      ];
    out[(size_t)row*DMD + t + 256] = (x1 - mean)*rstd*gamma[t + 256] + beta[t + 256];
    out[(size_t)row*DMD + t + 512] = (x2 - mean)*rstd*gamma[t + 512] + beta[t + 512];
}

// ---------------------------------------------------------------------------
extern "C" void kernel_launch(void* const* d_in, const int* in_sizes, int n_in,
                              void* d_out, int out_size)
{
    const float* hidden = (const float*)d_in[0];
    const float* cosb   = (const float*)d_in[1];
    const float* sinb   = (const float*)d_in[2];
    const float* Wq     = (const float*)d_in[3];
    const float* bq     = (const float*)d_in[4];
    const float* Wk     = (const float*)d_in[5];
    const float* bk     = (const float*)d_in[6];
    const float* Wv     = (const float*)d_in[7];
    const float* bv     = (const float*)d_in[8];
    const float* Wo     = (const float*)d_in[9];
    const float* ln_g   = (const float*)d_in[10];
    const float* ln_b   = (const float*)d_in[11];

    __nv_bfloat16 *qp, *kp, *vp, *ap, *xp, *wqp, *wkp, *wvp, *wop;
    float *tp;
    cudaGetSymbolAddress((void**)&qp,  g_q);
    cudaGetSymbolAddress((void**)&kp,  g_k);
    cudaGetSymbolAddress((void**)&vp,  g_v);
    cudaGetSymbolAddress((void**)&ap,  g_attn);
    cudaGetSymbolAddress((void**)&xp,  g_x);
    cudaGetSymbolAddress((void**)&wqp, g_wq);
    cudaGetSymbolAddress((void**)&wkp, g_wk);
    cudaGetSymbolAddress((void**)&wvp, g_wv);
    cudaGetSymbolAddress((void**)&wop, g_wo);
    cudaGetSymbolAddress((void**)&tp,  g_tmp);

    // Convert inputs to bf16 (hidden + all 4 weights fused)
    f2bf<<<(MROWS*DMD/4 + 255)/256, 256>>>(hidden, xp, MROWS*DMD);
    f2bf_w4<<<dim3((DMD*DMD/4 + 255)/256, 4), 256>>>(
        Wq, Wk, Wv, Wo, wqp, wkp, wvp, wop);

    // Fused QKV projections
    qkv_gemm<<<dim3(DMD/64, MROWS/128, 3), 256>>>(
        xp, wqp, wkp, wvp, bq, bk, bv, qp, kp, vp);

    rope_kernel<<<(BB*SS*NH*32)/256, 256>>>(qp, kp, cosb, sinb);

    cudaFuncSetAttribute(attn_mma,
                         cudaFuncAttributeMaxDynamicSharedMemorySize, ATTN_SMEM);
    attn_mma<<<dim3(SS/128, BB*NH), 128, ATTN_SMEM>>>(qp, kp, vp, ap);

    // out-proj + residual into tmp (fp32 for LN)
    oproj_gemm<<<dim3(DMD/64, MROWS/128), 256>>>(ap, wop, hidden, tp);

    ln_kernel<<<MROWS, 256>>>(tp, ln_g, ln_b, (float*)d_out);
}